// round 1
// baseline (speedup 1.0000x reference)
#include <cuda_runtime.h>
#include <math.h>

#define NNODES 50000
#define NEDGES 800000

// ---------------- scratch (static device globals; no allocations) ----------
__device__ float g_z[2 * NNODES * 256];      // per-etype GEMM output (max HF=256)
__device__ float g_h1[NNODES * 128];
__device__ float g_h2[NNODES * 64];
__device__ float g_el[2 * NNODES * 4];
__device__ float g_er[2 * NNODES * 4];
__device__ float g_m[2 * NNODES * 4];
__device__ float g_den[2 * NNODES * 4];
__device__ float g_ex[2 * NEDGES * 4];
__device__ float g_colsum[256];

// ---------------- helpers ----------------
__device__ __forceinline__ void atomicMaxF(float* addr, float val) {
    if (val >= 0.0f)
        atomicMax((int*)addr, __float_as_int(val));
    else
        atomicMin((unsigned int*)addr, __float_as_uint(val));
}

// ---------------- init kernels ----------------
__global__ void init_vec(float* p, float v, int n) {
    int i = blockIdx.x * blockDim.x + threadIdx.x;
    if (i < n) p[i] = v;
}

// out[n*F + f] = c0*b[f] + c1*b[F+f];  c from fc_w if given else 0.5/0.5
__global__ void init_bias(float* __restrict__ out, const float* __restrict__ b,
                          int F, const float* __restrict__ fc, int total) {
    int i = blockIdx.x * blockDim.x + threadIdx.x;
    if (i >= total) return;
    int f = i % F;
    float c0 = 0.5f, c1 = 0.5f;
    if (fc) { c0 = 0.5f * (fc[0] + fc[2]); c1 = 0.5f * (fc[1] + fc[3]); }
    out[i] = c0 * b[f] + c1 * b[F + f];
}

// ---------------- fused GEMM + attention logits ----------------
// Z = X(K) @ W(K,HF); el[n,h] = sum_f Z[n,h*FD+f]*al[h*FD+f]; er likewise.
template <int K, int HF, int H>
__global__ void __launch_bounds__(256)
gemm_att(const float* __restrict__ X, const float* __restrict__ W,
         const float* __restrict__ al, const float* __restrict__ ar,
         float* __restrict__ Z, float* __restrict__ el, float* __restrict__ er) {
    constexpr int TN = 8;
    constexpr int TX = HF / TN;        // threads per row-group in col dim
    constexpr int TY = 256 / TX;
    constexpr int TM = 4;
    constexpr int BM = TM * TY;        // rows per block
    constexpr int BK = 16;
    constexpr int FD = HF / H;         // feature dim per head
    constexpr int RW = TX / H;         // lanes reducing one head

    __shared__ float xs[BM][BK + 1];
    __shared__ float ws[BK][HF];

    int tid = threadIdx.x;
    int tx = tid % TX;
    int ty = tid / TX;
    int r0 = blockIdx.x * BM;

    float acc[TM][TN];
#pragma unroll
    for (int i = 0; i < TM; i++)
#pragma unroll
        for (int j = 0; j < TN; j++) acc[i][j] = 0.0f;

    for (int kb = 0; kb < K; kb += BK) {
        // load X tile
        for (int idx = tid; idx < BM * BK; idx += 256) {
            int r = idx / BK, c = idx % BK;
            int gr = r0 + r;
            xs[r][c] = (gr < NNODES) ? X[gr * K + kb + c] : 0.0f;
        }
        // load W tile (vectorized)
        for (int idx = tid; idx < BK * HF / 4; idx += 256) {
            int lin = idx * 4;
            int r = lin / HF, c = lin % HF;
            *(float4*)&ws[r][c] = *(const float4*)&W[(kb + r) * HF + c];
        }
        __syncthreads();
#pragma unroll
        for (int kk = 0; kk < BK; kk++) {
            float4 b0 = *(float4*)&ws[kk][tx * TN];
            float4 b1 = *(float4*)&ws[kk][tx * TN + 4];
            float bz[TN] = {b0.x, b0.y, b0.z, b0.w, b1.x, b1.y, b1.z, b1.w};
#pragma unroll
            for (int i = 0; i < TM; i++) {
                float a = xs[ty * TM + i][kk];
#pragma unroll
                for (int j = 0; j < TN; j++) acc[i][j] += a * bz[j];
            }
        }
        __syncthreads();
    }

    int cbase = tx * TN;
#pragma unroll
    for (int i = 0; i < TM; i++) {
        int row = r0 + ty * TM + i;
        float pl = 0.0f, pr = 0.0f;
#pragma unroll
        for (int j = 0; j < TN; j++) {
            pl += acc[i][j] * al[cbase + j];
            pr += acc[i][j] * ar[cbase + j];
        }
#pragma unroll
        for (int o = RW / 2; o > 0; o >>= 1) {
            pl += __shfl_xor_sync(0xffffffffu, pl, o);
            pr += __shfl_xor_sync(0xffffffffu, pr, o);
        }
        if (row < NNODES) {
            float4 v0 = {acc[i][0], acc[i][1], acc[i][2], acc[i][3]};
            float4 v1 = {acc[i][4], acc[i][5], acc[i][6], acc[i][7]};
            *(float4*)&Z[row * HF + cbase] = v0;
            *(float4*)&Z[row * HF + cbase + 4] = v1;
            if (tx % RW == 0) {
                int h = tx / RW;
                el[row * H + h] = pl;
                er[row * H + h] = pr;
            }
        }
    }
}

// ---------------- edge softmax passes ----------------
template <int H>
__global__ void edge_max(const int* __restrict__ src, const int* __restrict__ dst,
                         const float* __restrict__ el, const float* __restrict__ er,
                         float* __restrict__ m) {
    int e = blockIdx.x * blockDim.x + threadIdx.x;
    if (e >= NEDGES) return;
    int s = src[e], d = dst[e];
#pragma unroll
    for (int h = 0; h < H; h++) {
        float v = el[s * H + h] + er[d * H + h];
        v = (v > 0.0f) ? v : 0.2f * v;
        atomicMaxF(&m[d * H + h], v);
    }
}

template <int H>
__global__ void edge_exp(const int* __restrict__ src, const int* __restrict__ dst,
                         const float* __restrict__ el, const float* __restrict__ er,
                         const float* __restrict__ m, float* __restrict__ ex,
                         float* __restrict__ den) {
    int e = blockIdx.x * blockDim.x + threadIdx.x;
    if (e >= NEDGES) return;
    int s = src[e], d = dst[e];
#pragma unroll
    for (int h = 0; h < H; h++) {
        float v = el[s * H + h] + er[d * H + h];
        v = (v > 0.0f) ? v : 0.2f * v;
        float xv = __expf(v - m[d * H + h]);
        ex[e * H + h] = xv;
        atomicAdd(&den[d * H + h], xv);
    }
}

// ---------------- weighted scatter aggregation ----------------
// out[dst, :] += scale * (ex/den) * Z[src, :]
template <int HF, int H>
__global__ void __launch_bounds__(256)
aggregate(const int* __restrict__ src, const int* __restrict__ dst,
          const float* __restrict__ Z, const float* __restrict__ ex,
          const float* __restrict__ den, float* __restrict__ out,
          float scale, const float* __restrict__ fc, int et) {
    constexpr int TPE = HF / 4;       // threads per edge
    constexpr int EPB = 256 / TPE;    // edges per block
    int e = blockIdx.x * EPB + threadIdx.x / TPE;
    if (e >= NEDGES) return;
    int lane = threadIdx.x % TPE;
    int fb = lane * 4;
    int h = fb / (HF / H);
    int s = src[e], d = dst[e];
    float sc = scale;
    if (fc) sc = 0.5f * (fc[et] + fc[2 + et]);
    float a = ex[e * H + h] / fmaxf(den[d * H + h], 1e-9f) * sc;
    float4 zv = *(const float4*)&Z[s * HF + fb];
    float* o = &out[d * HF + fb];
    atomicAdd(o + 0, a * zv.x);
    atomicAdd(o + 1, a * zv.y);
    atomicAdd(o + 2, a * zv.z);
    atomicAdd(o + 3, a * zv.w);
}

// ---------------- final centering ----------------
__global__ void colsum_kernel(const float* __restrict__ out, float* __restrict__ cs) {
    const int RPB = 64;
    int c = threadIdx.x;
    int r0 = blockIdx.x * RPB;
    int r1 = r0 + RPB; if (r1 > NNODES) r1 = NNODES;
    float acc = 0.0f;
    for (int r = r0; r < r1; r++) acc += out[r * 256 + c];
    atomicAdd(&cs[c], acc);
}

__global__ void center_kernel(float* __restrict__ out, const float* __restrict__ cs) {
    int i = blockIdx.x * blockDim.x + threadIdx.x;
    if (i < NNODES * 256) out[i] -= cs[i & 255] * (1.0f / NNODES);
}

// ---------------- orchestration ----------------
extern "C" void kernel_launch(void* const* d_in, const int* in_sizes, int n_in,
                              void* d_out, int out_size) {
    const float* x   = (const float*)d_in[0];
    const int* src[2] = {(const int*)d_in[1], (const int*)d_in[3]};
    const int* dst[2] = {(const int*)d_in[2], (const int*)d_in[4]};
    const float* W1  = (const float*)d_in[5];
    const float* al1 = (const float*)d_in[6];
    const float* ar1 = (const float*)d_in[7];
    const float* b1  = (const float*)d_in[8];
    const float* W2  = (const float*)d_in[9];
    const float* al2 = (const float*)d_in[10];
    const float* ar2 = (const float*)d_in[11];
    const float* b2  = (const float*)d_in[12];
    const float* Wm  = (const float*)d_in[13];
    const float* alm = (const float*)d_in[14];
    const float* arm = (const float*)d_in[15];
    const float* bm  = (const float*)d_in[16];
    const float* fc  = (const float*)d_in[17];
    float* out = (float*)d_out;

    float *zb, *h1, *h2, *elb, *erb, *mb, *denb, *exb, *cs;
    cudaGetSymbolAddress((void**)&zb,   g_z);
    cudaGetSymbolAddress((void**)&h1,   g_h1);
    cudaGetSymbolAddress((void**)&h2,   g_h2);
    cudaGetSymbolAddress((void**)&elb,  g_el);
    cudaGetSymbolAddress((void**)&erb,  g_er);
    cudaGetSymbolAddress((void**)&mb,   g_m);
    cudaGetSymbolAddress((void**)&denb, g_den);
    cudaGetSymbolAddress((void**)&exb,  g_ex);
    cudaGetSymbolAddress((void**)&cs,   g_colsum);

    const int EG = (NEDGES + 255) / 256;        // 3125
    const float NEG_INF = -INFINITY;

    // ---------------- layer 1: x(128) -> h1(128), H=1 ----------------
    init_bias<<<(NNODES * 128 + 255) / 256, 256>>>(h1, b1, 128, nullptr, NNODES * 128);
    for (int et = 0; et < 2; et++) {
        float* z   = zb   + et * NNODES * 256;
        float* el  = elb  + et * NNODES * 4;
        float* er  = erb  + et * NNODES * 4;
        float* m   = mb   + et * NNODES * 4;
        float* den = denb + et * NNODES * 4;
        float* ex  = exb  + et * NEDGES * 4;
        init_vec<<<(NNODES + 255) / 256, 256>>>(m, NEG_INF, NNODES);
        init_vec<<<(NNODES + 255) / 256, 256>>>(den, 0.0f, NNODES);
        gemm_att<128, 128, 1><<<(NNODES + 63) / 64, 256>>>(
            x, W1 + et * 128 * 128, al1 + et * 128, ar1 + et * 128, z, el, er);
        edge_max<1><<<EG, 256>>>(src[et], dst[et], el, er, m);
        edge_exp<1><<<EG, 256>>>(src[et], dst[et], el, er, m, ex, den);
        aggregate<128, 1><<<NEDGES / 8, 256>>>(src[et], dst[et], z, ex, den, h1,
                                               0.5f, nullptr, et);
    }

    // ---------------- layer 2: h1(128) -> h2(64), H=1, fc-combined -------
    init_bias<<<(NNODES * 64 + 255) / 256, 256>>>(h2, b2, 64, fc, NNODES * 64);
    for (int et = 0; et < 2; et++) {
        float* z   = zb   + et * NNODES * 256;
        float* el  = elb  + et * NNODES * 4;
        float* er  = erb  + et * NNODES * 4;
        float* m   = mb   + et * NNODES * 4;
        float* den = denb + et * NNODES * 4;
        float* ex  = exb  + et * NEDGES * 4;
        init_vec<<<(NNODES + 255) / 256, 256>>>(m, NEG_INF, NNODES);
        init_vec<<<(NNODES + 255) / 256, 256>>>(den, 0.0f, NNODES);
        gemm_att<128, 64, 1><<<(NNODES + 127) / 128, 256>>>(
            h1, W2 + et * 128 * 64, al2 + et * 64, ar2 + et * 64, z, el, er);
        edge_max<1><<<EG, 256>>>(src[et], dst[et], el, er, m);
        edge_exp<1><<<EG, 256>>>(src[et], dst[et], el, er, m, ex, den);
        aggregate<64, 1><<<NEDGES / 16, 256>>>(src[et], dst[et], z, ex, den, h2,
                                               0.0f, fc, et);
    }

    // ---------------- layer MH: h2(64) -> out(4x64), H=4 ----------------
    init_bias<<<(NNODES * 256 + 255) / 256, 256>>>(out, bm, 256, nullptr, NNODES * 256);
    for (int et = 0; et < 2; et++) {
        float* z   = zb   + et * NNODES * 256;
        float* el  = elb  + et * NNODES * 4;
        float* er  = erb  + et * NNODES * 4;
        float* m   = mb   + et * NNODES * 4;
        float* den = denb + et * NNODES * 4;
        float* ex  = exb  + et * NEDGES * 4;
        init_vec<<<(NNODES * 4 + 255) / 256, 256>>>(m, NEG_INF, NNODES * 4);
        init_vec<<<(NNODES * 4 + 255) / 256, 256>>>(den, 0.0f, NNODES * 4);
        gemm_att<64, 256, 4><<<(NNODES + 31) / 32, 256>>>(
            h2, Wm + et * 64 * 256, alm + et * 256, arm + et * 256, z, el, er);
        edge_max<4><<<EG, 256>>>(src[et], dst[et], el, er, m);
        edge_exp<4><<<EG, 256>>>(src[et], dst[et], el, er, m, ex, den);
        aggregate<256, 4><<<NEDGES / 4, 256>>>(src[et], dst[et], z, ex, den, out,
                                               0.5f, nullptr, et);
    }

    // ---------------- final per-column mean centering -------------------
    init_vec<<<1, 256>>>(cs, 0.0f, 256);
    colsum_kernel<<<(NNODES + 63) / 64, 256>>>(out, cs);
    center_kernel<<<(NNODES * 256 + 255) / 256, 256>>>(out, cs);
}

// round 2
// speedup vs baseline: 2.6920x; 2.6920x over previous
#include <cuda_runtime.h>
#include <math.h>

#define NNODES 50000
#define NEDGES 800000
#define CH_SCAN 512
#define NB_SCAN ((NNODES + CH_SCAN - 1) / CH_SCAN)   // 98

// ---------------- scratch (static device globals; no allocations) ----------
__device__ float g_z[2 * NNODES * 256];      // per-etype GEMM output (max HF=256)
__device__ float g_h1[NNODES * 128];
__device__ float g_h2[NNODES * 64];
__device__ float g_el[2 * NNODES * 4];
__device__ float g_er[2 * NNODES * 4];
__device__ float g_colsum[256];
__device__ int   g_rp[2][NNODES + 1];        // CSR row pointers (by dst)
__device__ int   g_cs[2][NEDGES];            // CSR src indices
__device__ int   g_wp[2][NNODES];            // fill cursors
__device__ int   g_bsum[128];                // scan block sums

// ---------------- small utility kernels ----------------
__global__ void zero_int(int* p, int n) {
    int i = blockIdx.x * blockDim.x + threadIdx.x;
    if (i < n) p[i] = 0;
}
__global__ void zero_f(float* p, int n) {
    int i = blockIdx.x * blockDim.x + threadIdx.x;
    if (i < n) p[i] = 0.0f;
}

// ---------------- CSR build ----------------
__global__ void count_k(const int* __restrict__ dst, int* __restrict__ cnt) {
    int e = blockIdx.x * blockDim.x + threadIdx.x;
    if (e < NEDGES) atomicAdd(&cnt[dst[e]], 1);
}

__global__ void scan_local(int* __restrict__ rp, int* __restrict__ bsum) {
    __shared__ int s[CH_SCAN];
    int tid = threadIdx.x;
    int i = blockIdx.x * CH_SCAN + tid;
    int v = (i < NNODES) ? rp[i] : 0;
    s[tid] = v;
    __syncthreads();
    for (int off = 1; off < CH_SCAN; off <<= 1) {
        int t = (tid >= off) ? s[tid - off] : 0;
        __syncthreads();
        s[tid] += t;
        __syncthreads();
    }
    if (i < NNODES) rp[i] = s[tid] - v;              // exclusive
    if (tid == CH_SCAN - 1) bsum[blockIdx.x] = s[tid];
}

__global__ void scan_sums(int* __restrict__ bsum) {   // 1 block, 128 threads
    __shared__ int s[128];
    int tid = threadIdx.x;
    int v = (tid < NB_SCAN) ? bsum[tid] : 0;
    s[tid] = v;
    __syncthreads();
    for (int off = 1; off < 128; off <<= 1) {
        int t = (tid >= off) ? s[tid - off] : 0;
        __syncthreads();
        s[tid] += t;
        __syncthreads();
    }
    bsum[tid] = s[tid] - v;                           // exclusive
}

__global__ void scan_add(int* __restrict__ rp, const int* __restrict__ bsum) {
    int i = blockIdx.x * blockDim.x + threadIdx.x;
    if (i < NNODES) rp[i] += bsum[i / CH_SCAN];
    if (i == 0) rp[NNODES] = NEDGES;
}

__global__ void copy_wp(const int* __restrict__ rp, int* __restrict__ wp) {
    int i = blockIdx.x * blockDim.x + threadIdx.x;
    if (i < NNODES) wp[i] = rp[i];
}

__global__ void fill_k(const int* __restrict__ src, const int* __restrict__ dst,
                       int* __restrict__ wp, int* __restrict__ cs) {
    int e = blockIdx.x * blockDim.x + threadIdx.x;
    if (e >= NEDGES) return;
    int p = atomicAdd(&wp[dst[e]], 1);
    cs[p] = src[e];
}

// ---------------- fused GEMM + attention logits ----------------
// Z = X(K) @ W(K,HF); el[n,h] = sum_f Z[n,h*FD+f]*al[h*FD+f]; er likewise.
template <int K, int HF, int H>
__global__ void __launch_bounds__(256)
gemm_att(const float* __restrict__ X, const float* __restrict__ W,
         const float* __restrict__ al, const float* __restrict__ ar,
         float* __restrict__ Z, float* __restrict__ el, float* __restrict__ er) {
    constexpr int TN = 8;
    constexpr int TX = HF / TN;
    constexpr int TY = 256 / TX;
    constexpr int TM = 4;
    constexpr int BM = TM * TY;
    constexpr int BK = 16;
    constexpr int RW = TX / H;

    __shared__ float xs[BM][BK + 1];
    __shared__ float ws[BK][HF];

    int tid = threadIdx.x;
    int tx = tid % TX;
    int ty = tid / TX;
    int r0 = blockIdx.x * BM;

    float acc[TM][TN];
#pragma unroll
    for (int i = 0; i < TM; i++)
#pragma unroll
        for (int j = 0; j < TN; j++) acc[i][j] = 0.0f;

    for (int kb = 0; kb < K; kb += BK) {
        for (int idx = tid; idx < BM * BK; idx += 256) {
            int r = idx / BK, c = idx % BK;
            int gr = r0 + r;
            xs[r][c] = (gr < NNODES) ? X[gr * K + kb + c] : 0.0f;
        }
        for (int idx = tid; idx < BK * HF / 4; idx += 256) {
            int lin = idx * 4;
            int r = lin / HF, c = lin % HF;
            *(float4*)&ws[r][c] = *(const float4*)&W[(kb + r) * HF + c];
        }
        __syncthreads();
#pragma unroll
        for (int kk = 0; kk < BK; kk++) {
            float4 b0 = *(float4*)&ws[kk][tx * TN];
            float4 b1 = *(float4*)&ws[kk][tx * TN + 4];
            float bz[TN] = {b0.x, b0.y, b0.z, b0.w, b1.x, b1.y, b1.z, b1.w};
#pragma unroll
            for (int i = 0; i < TM; i++) {
                float a = xs[ty * TM + i][kk];
#pragma unroll
                for (int j = 0; j < TN; j++) acc[i][j] += a * bz[j];
            }
        }
        __syncthreads();
    }

    int cbase = tx * TN;
#pragma unroll
    for (int i = 0; i < TM; i++) {
        int row = r0 + ty * TM + i;
        float pl = 0.0f, pr = 0.0f;
#pragma unroll
        for (int j = 0; j < TN; j++) {
            pl += acc[i][j] * al[cbase + j];
            pr += acc[i][j] * ar[cbase + j];
        }
#pragma unroll
        for (int o = RW / 2; o > 0; o >>= 1) {
            pl += __shfl_xor_sync(0xffffffffu, pl, o);
            pr += __shfl_xor_sync(0xffffffffu, pr, o);
        }
        if (row < NNODES) {
            float4 v0 = {acc[i][0], acc[i][1], acc[i][2], acc[i][3]};
            float4 v1 = {acc[i][4], acc[i][5], acc[i][6], acc[i][7]};
            *(float4*)&Z[row * HF + cbase] = v0;
            *(float4*)&Z[row * HF + cbase + 4] = v1;
            if (tx % RW == 0) {
                int h = tx / RW;
                el[row * H + h] = pl;
                er[row * H + h] = pr;
            }
        }
    }
}

// ---------------- fused CSR softmax + gather aggregation ----------------
// One warp per dst node. Both etypes processed; out = c0*agg0 + c1*agg1 + bias.
template <int HF, int H>
__global__ void __launch_bounds__(256)
gat_agg(const int* __restrict__ rp0, const int* __restrict__ cs0,
        const int* __restrict__ rp1, const int* __restrict__ cs1,
        const float* __restrict__ z0, const float* __restrict__ z1,
        const float* __restrict__ el0, const float* __restrict__ er0,
        const float* __restrict__ el1, const float* __restrict__ er1,
        const float* __restrict__ bia,     // (2, HF)
        const float* __restrict__ fc,      // nullptr -> c=0.5; else fc combine
        float* __restrict__ out) {
    constexpr int VEC = HF / 32;
    int w = (blockIdx.x * blockDim.x + threadIdx.x) >> 5;
    if (w >= NNODES) return;
    int lane = threadIdx.x & 31;

    float c0 = 0.5f, c1 = 0.5f;
    if (fc) { c0 = 0.5f * (fc[0] + fc[2]); c1 = 0.5f * (fc[1] + fc[3]); }

    float acc[VEC];
#pragma unroll
    for (int i = 0; i < VEC; i++) acc[i] = 0.0f;

#pragma unroll
    for (int et = 0; et < 2; et++) {
        const int* rp = et ? rp1 : rp0;
        const int* cs = et ? cs1 : cs0;
        const float* z = et ? z1 : z0;
        const float* el = et ? el1 : el0;
        const float* er = et ? er1 : er0;
        float ce = et ? c1 : c0;

        int beg = rp[w];
        int deg = rp[w + 1] - beg;
        if (deg == 0) continue;

        float ern[H];
#pragma unroll
        for (int h = 0; h < H; h++) ern[h] = er[w * H + h];

        // pass A: per-head max (lanes parallel over edges)
        float m[H];
#pragma unroll
        for (int h = 0; h < H; h++) m[h] = -1e30f;
        for (int i = lane; i < deg; i += 32) {
            int s = cs[beg + i];
#pragma unroll
            for (int h = 0; h < H; h++) {
                float v = el[s * H + h] + ern[h];
                v = (v > 0.0f) ? v : 0.2f * v;
                m[h] = fmaxf(m[h], v);
            }
        }
#pragma unroll
        for (int h = 0; h < H; h++)
#pragma unroll
            for (int o = 16; o > 0; o >>= 1)
                m[h] = fmaxf(m[h], __shfl_xor_sync(0xffffffffu, m[h], o));

        // pass B: per-head denominator
        float den[H];
#pragma unroll
        for (int h = 0; h < H; h++) den[h] = 0.0f;
        for (int i = lane; i < deg; i += 32) {
            int s = cs[beg + i];
#pragma unroll
            for (int h = 0; h < H; h++) {
                float v = el[s * H + h] + ern[h];
                v = (v > 0.0f) ? v : 0.2f * v;
                den[h] += __expf(v - m[h]);
            }
        }
#pragma unroll
        for (int h = 0; h < H; h++)
#pragma unroll
            for (int o = 16; o > 0; o >>= 1)
                den[h] += __shfl_xor_sync(0xffffffffu, den[h], o);
        float inv[H];
#pragma unroll
        for (int h = 0; h < H; h++) inv[h] = ce / fmaxf(den[h], 1e-9f);

        // pass C: sequential over edges, lanes parallel over features
        int s = cs[beg];
        for (int i = 0; i < deg; i++) {
            int sn = (i + 1 < deg) ? cs[beg + i + 1] : 0;
            if constexpr (HF == 64) {
                float v = el[s] + ern[0];
                v = (v > 0.0f) ? v : 0.2f * v;
                float wt = __expf(v - m[0]) * inv[0];
                float2 zv = *(const float2*)&z[s * 64 + lane * 2];
                acc[0] += wt * zv.x;
                acc[1] += wt * zv.y;
            } else if constexpr (HF == 128) {
                float v = el[s] + ern[0];
                v = (v > 0.0f) ? v : 0.2f * v;
                float wt = __expf(v - m[0]) * inv[0];
                float4 zv = *(const float4*)&z[s * 128 + lane * 4];
                acc[0] += wt * zv.x;
                acc[1] += wt * zv.y;
                acc[2] += wt * zv.z;
                acc[3] += wt * zv.w;
            } else {  // HF == 256, H == 4
                int h0 = lane >> 4;
                int h1 = 2 + (lane >> 4);
                float v0 = el[s * 4 + h0] + ern[h0];
                v0 = (v0 > 0.0f) ? v0 : 0.2f * v0;
                float w0 = __expf(v0 - m[h0]) * inv[h0];
                float v1 = el[s * 4 + h1] + ern[h1];
                v1 = (v1 > 0.0f) ? v1 : 0.2f * v1;
                float w1 = __expf(v1 - m[h1]) * inv[h1];
                float4 za = *(const float4*)&z[s * 256 + lane * 4];
                float4 zb = *(const float4*)&z[s * 256 + 128 + lane * 4];
                acc[0] += w0 * za.x;
                acc[1] += w0 * za.y;
                acc[2] += w0 * za.z;
                acc[3] += w0 * za.w;
                acc[4] += w1 * zb.x;
                acc[5] += w1 * zb.y;
                acc[6] += w1 * zb.z;
                acc[7] += w1 * zb.w;
            }
            s = sn;
        }
    }

    // write output with combined bias
    if constexpr (HF == 64) {
        int f = lane * 2;
        float2 o;
        o.x = acc[0] + c0 * bia[f] + c1 * bia[64 + f];
        o.y = acc[1] + c0 * bia[f + 1] + c1 * bia[64 + f + 1];
        *(float2*)&out[w * 64 + f] = o;
    } else if constexpr (HF == 128) {
        int f = lane * 4;
        float4 o;
        o.x = acc[0] + c0 * bia[f + 0] + c1 * bia[128 + f + 0];
        o.y = acc[1] + c0 * bia[f + 1] + c1 * bia[128 + f + 1];
        o.z = acc[2] + c0 * bia[f + 2] + c1 * bia[128 + f + 2];
        o.w = acc[3] + c0 * bia[f + 3] + c1 * bia[128 + f + 3];
        *(float4*)&out[w * 128 + f] = o;
    } else {
        int f = lane * 4;
        float4 o0, o1;
        o0.x = acc[0] + c0 * bia[f + 0] + c1 * bia[256 + f + 0];
        o0.y = acc[1] + c0 * bia[f + 1] + c1 * bia[256 + f + 1];
        o0.z = acc[2] + c0 * bia[f + 2] + c1 * bia[256 + f + 2];
        o0.w = acc[3] + c0 * bia[f + 3] + c1 * bia[256 + f + 3];
        o1.x = acc[4] + c0 * bia[128 + f + 0] + c1 * bia[256 + 128 + f + 0];
        o1.y = acc[5] + c0 * bia[128 + f + 1] + c1 * bia[256 + 128 + f + 1];
        o1.z = acc[6] + c0 * bia[128 + f + 2] + c1 * bia[256 + 128 + f + 2];
        o1.w = acc[7] + c0 * bia[128 + f + 3] + c1 * bia[256 + 128 + f + 3];
        *(float4*)&out[w * 256 + f] = o0;
        *(float4*)&out[w * 256 + 128 + f] = o1;
    }
}

// ---------------- final centering ----------------
__global__ void colsum_kernel(const float* __restrict__ out, float* __restrict__ cs) {
    const int RPB = 64;
    int c = threadIdx.x;
    int r0 = blockIdx.x * RPB;
    int r1 = r0 + RPB; if (r1 > NNODES) r1 = NNODES;
    float acc = 0.0f;
    for (int r = r0; r < r1; r++) acc += out[r * 256 + c];
    atomicAdd(&cs[c], acc);
}

__global__ void center_kernel(float* __restrict__ out, const float* __restrict__ cs) {
    int i = blockIdx.x * blockDim.x + threadIdx.x;
    if (i < NNODES * 256) out[i] -= cs[i & 255] * (1.0f / NNODES);
}

// ---------------- orchestration ----------------
extern "C" void kernel_launch(void* const* d_in, const int* in_sizes, int n_in,
                              void* d_out, int out_size) {
    const float* x   = (const float*)d_in[0];
    const int* src[2] = {(const int*)d_in[1], (const int*)d_in[3]};
    const int* dst[2] = {(const int*)d_in[2], (const int*)d_in[4]};
    const float* W1  = (const float*)d_in[5];
    const float* al1 = (const float*)d_in[6];
    const float* ar1 = (const float*)d_in[7];
    const float* b1  = (const float*)d_in[8];
    const float* W2  = (const float*)d_in[9];
    const float* al2 = (const float*)d_in[10];
    const float* ar2 = (const float*)d_in[11];
    const float* b2  = (const float*)d_in[12];
    const float* Wm  = (const float*)d_in[13];
    const float* alm = (const float*)d_in[14];
    const float* arm = (const float*)d_in[15];
    const float* bm  = (const float*)d_in[16];
    const float* fc  = (const float*)d_in[17];
    float* out = (float*)d_out;

    float *zb, *h1, *h2, *elb, *erb, *csum;
    int *rp[2], *cse[2], *wp[2], *bsum;
    cudaGetSymbolAddress((void**)&zb,   g_z);
    cudaGetSymbolAddress((void**)&h1,   g_h1);
    cudaGetSymbolAddress((void**)&h2,   g_h2);
    cudaGetSymbolAddress((void**)&elb,  g_el);
    cudaGetSymbolAddress((void**)&erb,  g_er);
    cudaGetSymbolAddress((void**)&csum, g_colsum);
    {
        int* base;
        cudaGetSymbolAddress((void**)&base, g_rp);
        rp[0] = base; rp[1] = base + (NNODES + 1);
        cudaGetSymbolAddress((void**)&base, g_cs);
        cse[0] = base; cse[1] = base + NEDGES;
        cudaGetSymbolAddress((void**)&base, g_wp);
        wp[0] = base; wp[1] = base + NNODES;
        cudaGetSymbolAddress((void**)&bsum, g_bsum);
    }

    const int EG = (NEDGES + 255) / 256;
    const int NG = (NNODES + 255) / 256;
    const int AGG_BLOCKS = (NNODES * 32 + 255) / 256;   // one warp per node

    // ---------------- CSR build (by dst) for both etypes ----------------
    for (int et = 0; et < 2; et++) {
        zero_int<<<NG, 256>>>(rp[et], NNODES);
        count_k<<<EG, 256>>>(dst[et], rp[et]);
        scan_local<<<NB_SCAN, CH_SCAN>>>(rp[et], bsum);
        scan_sums<<<1, 128>>>(bsum);
        scan_add<<<NG, 256>>>(rp[et], bsum);
        copy_wp<<<NG, 256>>>(rp[et], wp[et]);
        fill_k<<<EG, 256>>>(src[et], dst[et], wp[et], cse[et]);
    }

    float* z[2]  = {zb, zb + NNODES * 256};
    float* el[2] = {elb, elb + NNODES * 4};
    float* er[2] = {erb, erb + NNODES * 4};

    // ---------------- layer 1: x(128) -> h1(128), H=1 ----------------
    for (int et = 0; et < 2; et++)
        gemm_att<128, 128, 1><<<(NNODES + 63) / 64, 256>>>(
            x, W1 + et * 128 * 128, al1 + et * 128, ar1 + et * 128,
            z[et], el[et], er[et]);
    gat_agg<128, 1><<<AGG_BLOCKS, 256>>>(
        rp[0], cse[0], rp[1], cse[1], z[0], z[1],
        el[0], er[0], el[1], er[1], b1, nullptr, h1);

    // ---------------- layer 2: h1(128) -> h2(64), H=1, fc combine -------
    for (int et = 0; et < 2; et++)
        gemm_att<128, 64, 1><<<(NNODES + 127) / 128, 256>>>(
            h1, W2 + et * 128 * 64, al2 + et * 64, ar2 + et * 64,
            z[et], el[et], er[et]);
    gat_agg<64, 1><<<AGG_BLOCKS, 256>>>(
        rp[0], cse[0], rp[1], cse[1], z[0], z[1],
        el[0], er[0], el[1], er[1], b2, fc, h2);

    // ---------------- layer MH: h2(64) -> out(4x64), H=4 ----------------
    for (int et = 0; et < 2; et++)
        gemm_att<64, 256, 4><<<(NNODES + 31) / 32, 256>>>(
            h2, Wm + et * 64 * 256, alm + et * 256, arm + et * 256,
            z[et], el[et], er[et]);
    gat_agg<256, 4><<<AGG_BLOCKS, 256>>>(
        rp[0], cse[0], rp[1], cse[1], z[0], z[1],
        el[0], er[0], el[1], er[1], bm, nullptr, out);

    // ---------------- final per-column mean centering -------------------
    zero_f<<<1, 256>>>(csum, 256);
    colsum_kernel<<<(NNODES + 63) / 64, 256>>>(out, csum);
    center_kernel<<<(NNODES * 256 + 255) / 256, 256>>>(out, csum);
}

// round 3
// speedup vs baseline: 3.5981x; 1.3366x over previous
#include <cuda_runtime.h>
#include <math.h>

#define NNODES 50000
#define NEDGES 800000
#define CH_SCAN 512
#define NB_SCAN ((NNODES + CH_SCAN - 1) / CH_SCAN)   // 98

// ---------------- scratch (static device globals; no allocations) ----------
__device__ float g_z[2 * NNODES * 256];
__device__ float g_h1[NNODES * 128];
__device__ float g_h2[NNODES * 64];
__device__ float g_el[2 * NNODES * 4];
__device__ float g_er[2 * NNODES * 4];
__device__ float g_colsum[256];
__device__ int   g_rp[2][NNODES + 1];        // CSR row pointers (by dst)
__device__ int   g_cse[2][NEDGES];           // CSR src indices
__device__ int   g_wp[2][NNODES];            // fill cursors
__device__ int   g_bsum[2][128];             // scan block sums

// ---------------- small utility kernels ----------------
__global__ void zero_int(int* p, int n) {
    int i = blockIdx.x * blockDim.x + threadIdx.x;
    if (i < n) p[i] = 0;
}
__global__ void zero_f(float* p, int n) {
    int i = blockIdx.x * blockDim.x + threadIdx.x;
    if (i < n) p[i] = 0.0f;
}

// ---------------- CSR build (both etypes via blockIdx.y) ----------------
__global__ void count_k(const int* __restrict__ d0, const int* __restrict__ d1,
                        int* __restrict__ rpb) {
    int e = blockIdx.x * blockDim.x + threadIdx.x;
    if (e >= NEDGES) return;
    const int* dst = blockIdx.y ? d1 : d0;
    atomicAdd(&rpb[blockIdx.y * (NNODES + 1) + dst[e]], 1);
}

__global__ void scan_local(int* __restrict__ rpb, int* __restrict__ bsumb) {
    __shared__ int s[CH_SCAN];
    int* rp = rpb + blockIdx.y * (NNODES + 1);
    int* bsum = bsumb + blockIdx.y * 128;
    int tid = threadIdx.x;
    int i = blockIdx.x * CH_SCAN + tid;
    int v = (i < NNODES) ? rp[i] : 0;
    s[tid] = v;
    __syncthreads();
    for (int off = 1; off < CH_SCAN; off <<= 1) {
        int t = (tid >= off) ? s[tid - off] : 0;
        __syncthreads();
        s[tid] += t;
        __syncthreads();
    }
    if (i < NNODES) rp[i] = s[tid] - v;              // exclusive
    if (tid == CH_SCAN - 1) bsum[blockIdx.x] = s[tid];
}

__global__ void scan_sums(int* __restrict__ bsumb) {  // grid=2, block=128
    __shared__ int s[128];
    int* bsum = bsumb + blockIdx.x * 128;
    int tid = threadIdx.x;
    int v = (tid < NB_SCAN) ? bsum[tid] : 0;
    s[tid] = v;
    __syncthreads();
    for (int off = 1; off < 128; off <<= 1) {
        int t = (tid >= off) ? s[tid - off] : 0;
        __syncthreads();
        s[tid] += t;
        __syncthreads();
    }
    bsum[tid] = s[tid] - v;                           // exclusive
}

__global__ void scan_add_wp(int* __restrict__ rpb, const int* __restrict__ bsumb,
                            int* __restrict__ wpb) {
    int i = blockIdx.x * blockDim.x + threadIdx.x;
    int* rp = rpb + blockIdx.y * (NNODES + 1);
    int* wp = wpb + blockIdx.y * NNODES;
    if (i < NNODES) {
        int v = rp[i] + bsumb[blockIdx.y * 128 + i / CH_SCAN];
        rp[i] = v;
        wp[i] = v;
    }
    if (i == 0) rp[NNODES] = NEDGES;
}

__global__ void fill_k(const int* __restrict__ s0, const int* __restrict__ s1,
                       const int* __restrict__ d0, const int* __restrict__ d1,
                       int* __restrict__ wpb, int* __restrict__ csb) {
    int e = blockIdx.x * blockDim.x + threadIdx.x;
    if (e >= NEDGES) return;
    const int* src = blockIdx.y ? s1 : s0;
    const int* dst = blockIdx.y ? d1 : d0;
    int* wp = wpb + blockIdx.y * NNODES;
    int* cs = csb + blockIdx.y * NEDGES;
    int p = atomicAdd(&wp[dst[e]], 1);
    cs[p] = src[e];
}

// ---------------- fused GEMM + attention logits (both etypes, TM=8) ----------
template <int K, int HF, int H>
__global__ void __launch_bounds__(256)
gemm_att(const float* __restrict__ X, const float* __restrict__ Wb,
         const float* __restrict__ alb, const float* __restrict__ arb,
         float* __restrict__ Zb, float* __restrict__ elb, float* __restrict__ erb) {
    constexpr int TN = 8;
    constexpr int TX = HF / TN;
    constexpr int TY = 256 / TX;
    constexpr int TM = 8;
    constexpr int BM = TM * TY;
    constexpr int BK = 16;
    constexpr int RW = TX / H;

    const float* W  = Wb  + blockIdx.y * K * HF;
    const float* al = alb + blockIdx.y * HF;
    const float* ar = arb + blockIdx.y * HF;
    float* Z  = Zb  + blockIdx.y * (NNODES * 256);
    float* el = elb + blockIdx.y * (NNODES * 4);
    float* er = erb + blockIdx.y * (NNODES * 4);

    __shared__ float xs[BM][BK + 1];
    __shared__ float ws[BK][HF];

    int tid = threadIdx.x;
    int tx = tid % TX;
    int ty = tid / TX;
    int r0 = blockIdx.x * BM;

    float acc[TM][TN];
#pragma unroll
    for (int i = 0; i < TM; i++)
#pragma unroll
        for (int j = 0; j < TN; j++) acc[i][j] = 0.0f;

    for (int kb = 0; kb < K; kb += BK) {
        // X tile (float4 loads, scalar stores due to +1 padding)
        for (int idx = tid * 4; idx < BM * BK; idx += 1024) {
            int r = idx / BK, c = idx % BK;
            int gr = r0 + r;
            float4 v = make_float4(0.f, 0.f, 0.f, 0.f);
            if (gr < NNODES) v = *(const float4*)&X[gr * K + kb + c];
            xs[r][c] = v.x; xs[r][c + 1] = v.y; xs[r][c + 2] = v.z; xs[r][c + 3] = v.w;
        }
        // W tile
        for (int idx = tid; idx < BK * HF / 4; idx += 256) {
            int lin = idx * 4;
            int r = lin / HF, c = lin % HF;
            *(float4*)&ws[r][c] = *(const float4*)&W[(kb + r) * HF + c];
        }
        __syncthreads();
#pragma unroll
        for (int kk = 0; kk < BK; kk++) {
            float4 b0 = *(float4*)&ws[kk][tx * TN];
            float4 b1 = *(float4*)&ws[kk][tx * TN + 4];
            float bz[TN] = {b0.x, b0.y, b0.z, b0.w, b1.x, b1.y, b1.z, b1.w};
#pragma unroll
            for (int i = 0; i < TM; i++) {
                float a = xs[ty * TM + i][kk];
#pragma unroll
                for (int j = 0; j < TN; j++) acc[i][j] += a * bz[j];
            }
        }
        __syncthreads();
    }

    int cbase = tx * TN;
#pragma unroll
    for (int i = 0; i < TM; i++) {
        int row = r0 + ty * TM + i;
        float pl = 0.0f, pr = 0.0f;
#pragma unroll
        for (int j = 0; j < TN; j++) {
            pl += acc[i][j] * al[cbase + j];
            pr += acc[i][j] * ar[cbase + j];
        }
#pragma unroll
        for (int o = RW / 2; o > 0; o >>= 1) {
            pl += __shfl_xor_sync(0xffffffffu, pl, o);
            pr += __shfl_xor_sync(0xffffffffu, pr, o);
        }
        if (row < NNODES) {
            float4 v0 = {acc[i][0], acc[i][1], acc[i][2], acc[i][3]};
            float4 v1 = {acc[i][4], acc[i][5], acc[i][6], acc[i][7]};
            *(float4*)&Z[row * HF + cbase] = v0;
            *(float4*)&Z[row * HF + cbase + 4] = v1;
            if (tx % RW == 0) {
                int h = tx / RW;
                el[row * H + h] = pl;
                er[row * H + h] = pr;
            }
        }
    }
}

// ---------------- single-pass CSR softmax + gather aggregation ----------------
// One warp per dst node; no max subtraction (exact for softmax ratio), no
// warp reductions (den is lane-redundant within each head group).
__device__ __forceinline__ float lrelu(float v) {
    return (v > 0.0f) ? v : 0.2f * v;
}

template <int HF, int H>
__global__ void __launch_bounds__(256)
gat_agg(const int* __restrict__ rp0, const int* __restrict__ cs0,
        const int* __restrict__ rp1, const int* __restrict__ cs1,
        const float* __restrict__ z0, const float* __restrict__ z1,
        const float* __restrict__ el0, const float* __restrict__ er0,
        const float* __restrict__ el1, const float* __restrict__ er1,
        const float* __restrict__ bia,     // (2, HF)
        const float* __restrict__ fc,      // nullptr -> c=0.5; else fc combine
        float* __restrict__ out) {
    constexpr int VEC = HF / 32;
    int w = (blockIdx.x * blockDim.x + threadIdx.x) >> 5;
    if (w >= NNODES) return;
    int lane = threadIdx.x & 31;

    float c0 = 0.5f, c1 = 0.5f;
    if (fc) { c0 = 0.5f * (fc[0] + fc[2]); c1 = 0.5f * (fc[1] + fc[3]); }

    float acc[VEC];
#pragma unroll
    for (int i = 0; i < VEC; i++) acc[i] = 0.0f;

#pragma unroll
    for (int et = 0; et < 2; et++) {
        const int* rp = et ? rp1 : rp0;
        const int* cs = et ? cs1 : cs0;
        const float* z = et ? z1 : z0;
        const float* el = et ? el1 : el0;
        const float* er = et ? er1 : er0;
        float ce = et ? c1 : c0;

        int beg = rp[w];
        int end = rp[w + 1];
        if (beg == end) continue;

        float accE[VEC];
#pragma unroll
        for (int i = 0; i < VEC; i++) accE[i] = 0.0f;

        if constexpr (H == 1) {
            float ern = er[w];
            float den = 0.0f;
            int i = beg;
            for (; i + 4 <= end; i += 4) {
                int sa = cs[i], sb = cs[i + 1], sc = cs[i + 2], sd = cs[i + 3];
                float wa = __expf(lrelu(el[sa] + ern));
                float wb = __expf(lrelu(el[sb] + ern));
                float wc = __expf(lrelu(el[sc] + ern));
                float wd = __expf(lrelu(el[sd] + ern));
                if constexpr (HF == 128) {
                    float4 Za = *(const float4*)&z[sa * 128 + lane * 4];
                    float4 Zb = *(const float4*)&z[sb * 128 + lane * 4];
                    float4 Zc = *(const float4*)&z[sc * 128 + lane * 4];
                    float4 Zd = *(const float4*)&z[sd * 128 + lane * 4];
                    accE[0] += wa * Za.x + wb * Zb.x + wc * Zc.x + wd * Zd.x;
                    accE[1] += wa * Za.y + wb * Zb.y + wc * Zc.y + wd * Zd.y;
                    accE[2] += wa * Za.z + wb * Zb.z + wc * Zc.z + wd * Zd.z;
                    accE[3] += wa * Za.w + wb * Zb.w + wc * Zc.w + wd * Zd.w;
                } else {  // HF == 64
                    float2 Za = *(const float2*)&z[sa * 64 + lane * 2];
                    float2 Zb = *(const float2*)&z[sb * 64 + lane * 2];
                    float2 Zc = *(const float2*)&z[sc * 64 + lane * 2];
                    float2 Zd = *(const float2*)&z[sd * 64 + lane * 2];
                    accE[0] += wa * Za.x + wb * Zb.x + wc * Zc.x + wd * Zd.x;
                    accE[1] += wa * Za.y + wb * Zb.y + wc * Zc.y + wd * Zd.y;
                }
                den += wa + wb + wc + wd;
            }
            for (; i < end; i++) {
                int s = cs[i];
                float wt = __expf(lrelu(el[s] + ern));
                den += wt;
                if constexpr (HF == 128) {
                    float4 Zv = *(const float4*)&z[s * 128 + lane * 4];
                    accE[0] += wt * Zv.x; accE[1] += wt * Zv.y;
                    accE[2] += wt * Zv.z; accE[3] += wt * Zv.w;
                } else {
                    float2 Zv = *(const float2*)&z[s * 64 + lane * 2];
                    accE[0] += wt * Zv.x; accE[1] += wt * Zv.y;
                }
            }
            float sc1 = ce / fmaxf(den, 1e-30f);
#pragma unroll
            for (int j = 0; j < VEC; j++) acc[j] += accE[j] * sc1;
        } else {  // H == 4, HF == 256
            int h0 = lane >> 4;
            int h1 = 2 + (lane >> 4);
            float ern0 = er[w * 4 + h0];
            float ern1 = er[w * 4 + h1];
            float den0 = 0.0f, den1 = 0.0f;
            int i = beg;
            for (; i + 2 <= end; i += 2) {
                int sa = cs[i], sb = cs[i + 1];
                float wa0 = __expf(lrelu(el[sa * 4 + h0] + ern0));
                float wa1 = __expf(lrelu(el[sa * 4 + h1] + ern1));
                float wb0 = __expf(lrelu(el[sb * 4 + h0] + ern0));
                float wb1 = __expf(lrelu(el[sb * 4 + h1] + ern1));
                float4 Za0 = *(const float4*)&z[sa * 256 + lane * 4];
                float4 Za1 = *(const float4*)&z[sa * 256 + 128 + lane * 4];
                float4 Zb0 = *(const float4*)&z[sb * 256 + lane * 4];
                float4 Zb1 = *(const float4*)&z[sb * 256 + 128 + lane * 4];
                accE[0] += wa0 * Za0.x + wb0 * Zb0.x;
                accE[1] += wa0 * Za0.y + wb0 * Zb0.y;
                accE[2] += wa0 * Za0.z + wb0 * Zb0.z;
                accE[3] += wa0 * Za0.w + wb0 * Zb0.w;
                accE[4] += wa1 * Za1.x + wb1 * Zb1.x;
                accE[5] += wa1 * Za1.y + wb1 * Zb1.y;
                accE[6] += wa1 * Za1.z + wb1 * Zb1.z;
                accE[7] += wa1 * Za1.w + wb1 * Zb1.w;
                den0 += wa0 + wb0;
                den1 += wa1 + wb1;
            }
            for (; i < end; i++) {
                int s = cs[i];
                float w0 = __expf(lrelu(el[s * 4 + h0] + ern0));
                float w1 = __expf(lrelu(el[s * 4 + h1] + ern1));
                float4 Z0 = *(const float4*)&z[s * 256 + lane * 4];
                float4 Z1 = *(const float4*)&z[s * 256 + 128 + lane * 4];
                accE[0] += w0 * Z0.x; accE[1] += w0 * Z0.y;
                accE[2] += w0 * Z0.z; accE[3] += w0 * Z0.w;
                accE[4] += w1 * Z1.x; accE[5] += w1 * Z1.y;
                accE[6] += w1 * Z1.z; accE[7] += w1 * Z1.w;
                den0 += w0;
                den1 += w1;
            }
            float s0 = ce / fmaxf(den0, 1e-30f);
            float s1 = ce / fmaxf(den1, 1e-30f);
#pragma unroll
            for (int j = 0; j < 4; j++) acc[j] += accE[j] * s0;
#pragma unroll
            for (int j = 4; j < 8; j++) acc[j] += accE[j] * s1;
        }
    }

    // write output with combined bias
    if constexpr (HF == 64) {
        int f = lane * 2;
        float2 o;
        o.x = acc[0] + c0 * bia[f] + c1 * bia[64 + f];
        o.y = acc[1] + c0 * bia[f + 1] + c1 * bia[64 + f + 1];
        *(float2*)&out[w * 64 + f] = o;
    } else if constexpr (HF == 128) {
        int f = lane * 4;
        float4 o;
        o.x = acc[0] + c0 * bia[f + 0] + c1 * bia[128 + f + 0];
        o.y = acc[1] + c0 * bia[f + 1] + c1 * bia[128 + f + 1];
        o.z = acc[2] + c0 * bia[f + 2] + c1 * bia[128 + f + 2];
        o.w = acc[3] + c0 * bia[f + 3] + c1 * bia[128 + f + 3];
        *(float4*)&out[w * 128 + f] = o;
    } else {
        int f = lane * 4;
        float4 o0, o1;
        o0.x = acc[0] + c0 * bia[f + 0] + c1 * bia[256 + f + 0];
        o0.y = acc[1] + c0 * bia[f + 1] + c1 * bia[256 + f + 1];
        o0.z = acc[2] + c0 * bia[f + 2] + c1 * bia[256 + f + 2];
        o0.w = acc[3] + c0 * bia[f + 3] + c1 * bia[256 + f + 3];
        o1.x = acc[4] + c0 * bia[128 + f + 0] + c1 * bia[256 + 128 + f + 0];
        o1.y = acc[5] + c0 * bia[128 + f + 1] + c1 * bia[256 + 128 + f + 1];
        o1.z = acc[6] + c0 * bia[128 + f + 2] + c1 * bia[256 + 128 + f + 2];
        o1.w = acc[7] + c0 * bia[128 + f + 3] + c1 * bia[256 + 128 + f + 3];
        *(float4*)&out[w * 256 + f] = o0;
        *(float4*)&out[w * 256 + 128 + f] = o1;
    }
}

// ---------------- final centering ----------------
__global__ void colsum_kernel(const float* __restrict__ out, float* __restrict__ cs) {
    const int RPB = 64;
    int c = threadIdx.x;
    int r0 = blockIdx.x * RPB;
    int r1 = r0 + RPB; if (r1 > NNODES) r1 = NNODES;
    float acc = 0.0f;
    for (int r = r0; r < r1; r++) acc += out[r * 256 + c];
    atomicAdd(&cs[c], acc);
}

__global__ void center_kernel(float* __restrict__ out, const float* __restrict__ cs) {
    int i = blockIdx.x * blockDim.x + threadIdx.x;
    if (i < NNODES * 256) out[i] -= cs[i & 255] * (1.0f / NNODES);
}

// ---------------- orchestration ----------------
extern "C" void kernel_launch(void* const* d_in, const int* in_sizes, int n_in,
                              void* d_out, int out_size) {
    const float* x   = (const float*)d_in[0];
    const int* src0 = (const int*)d_in[1];
    const int* dst0 = (const int*)d_in[2];
    const int* src1 = (const int*)d_in[3];
    const int* dst1 = (const int*)d_in[4];
    const float* W1  = (const float*)d_in[5];
    const float* al1 = (const float*)d_in[6];
    const float* ar1 = (const float*)d_in[7];
    const float* b1  = (const float*)d_in[8];
    const float* W2  = (const float*)d_in[9];
    const float* al2 = (const float*)d_in[10];
    const float* ar2 = (const float*)d_in[11];
    const float* b2  = (const float*)d_in[12];
    const float* Wm  = (const float*)d_in[13];
    const float* alm = (const float*)d_in[14];
    const float* arm = (const float*)d_in[15];
    const float* bm  = (const float*)d_in[16];
    const float* fc  = (const float*)d_in[17];
    float* out = (float*)d_out;

    float *zb, *h1, *h2, *elb, *erb, *csum;
    int *rpb, *cseb, *wpb, *bsumb;
    cudaGetSymbolAddress((void**)&zb,    g_z);
    cudaGetSymbolAddress((void**)&h1,    g_h1);
    cudaGetSymbolAddress((void**)&h2,    g_h2);
    cudaGetSymbolAddress((void**)&elb,   g_el);
    cudaGetSymbolAddress((void**)&erb,   g_er);
    cudaGetSymbolAddress((void**)&csum,  g_colsum);
    cudaGetSymbolAddress((void**)&rpb,   g_rp);
    cudaGetSymbolAddress((void**)&cseb,  g_cse);
    cudaGetSymbolAddress((void**)&wpb,   g_wp);
    cudaGetSymbolAddress((void**)&bsumb, g_bsum);

    int* rp[2]  = {rpb, rpb + (NNODES + 1)};
    int* cse[2] = {cseb, cseb + NEDGES};
    float* z[2]  = {zb, zb + NNODES * 256};
    float* el[2] = {elb, elb + NNODES * 4};
    float* er[2] = {erb, erb + NNODES * 4};

    const int EG = (NEDGES + 255) / 256;
    const int NG = (NNODES + 255) / 256;
    const int AGG_BLOCKS = (NNODES * 32 + 255) / 256;

    // ---------------- CSR build (by dst), both etypes per launch -----------
    zero_int<<<(2 * (NNODES + 1) + 255) / 256, 256>>>(rpb, 2 * (NNODES + 1));
    count_k<<<dim3(EG, 2), 256>>>(dst0, dst1, rpb);
    scan_local<<<dim3(NB_SCAN, 2), CH_SCAN>>>(rpb, bsumb);
    scan_sums<<<2, 128>>>(bsumb);
    scan_add_wp<<<dim3(NG, 2), 256>>>(rpb, bsumb, wpb);
    fill_k<<<dim3(EG, 2), 256>>>(src0, src1, dst0, dst1, wpb, cseb);

    // ---------------- layer 1: x(128) -> h1(128), H=1 ----------------
    gemm_att<128, 128, 1><<<dim3((NNODES + 127) / 128, 2), 256>>>(
        x, W1, al1, ar1, zb, elb, erb);
    gat_agg<128, 1><<<AGG_BLOCKS, 256>>>(
        rp[0], cse[0], rp[1], cse[1], z[0], z[1],
        el[0], er[0], el[1], er[1], b1, nullptr, h1);

    // ---------------- layer 2: h1(128) -> h2(64), H=1, fc combine -------
    gemm_att<128, 64, 1><<<dim3((NNODES + 255) / 256, 2), 256>>>(
        h1, W2, al2, ar2, zb, elb, erb);
    gat_agg<64, 1><<<AGG_BLOCKS, 256>>>(
        rp[0], cse[0], rp[1], cse[1], z[0], z[1],
        el[0], er[0], el[1], er[1], b2, fc, h2);

    // ---------------- layer MH: h2(64) -> out(4x64), H=4 ----------------
    gemm_att<64, 256, 4><<<dim3((NNODES + 63) / 64, 2), 256>>>(
        h2, Wm, alm, arm, zb, elb, erb);
    gat_agg<256, 4><<<AGG_BLOCKS, 256>>>(
        rp[0], cse[0], rp[1], cse[1], z[0], z[1],
        el[0], er[0], el[1], er[1], bm, nullptr, out);

    // ---------------- final per-column mean centering -------------------
    zero_f<<<1, 256>>>(csum, 256);
    colsum_kernel<<<(NNODES + 63) / 64, 256>>>(out, csum);
    center_kernel<<<(NNODES * 256 + 255) / 256, 256>>>(out, csum);
}

// round 4
// speedup vs baseline: 4.1308x; 1.1481x over previous
#include <cuda_runtime.h>
#include <cuda_fp16.h>
#include <math.h>

#define NNODES 50000
#define NEDGES 800000
#define CH_SCAN 512
#define NB_SCAN ((NNODES + CH_SCAN - 1) / CH_SCAN)   // 98

// ---------------- scratch (static device globals; no allocations) ----------
__device__ __half g_z[2 * NNODES * 256];     // fp16 per-etype GEMM output
__device__ float g_h1[NNODES * 128];
__device__ float g_h2[NNODES * 64];
__device__ float g_el[2 * NNODES * 4];
__device__ float g_er[2 * NNODES * 4];
__device__ float g_colsum[256];
__device__ int   g_rp[2][NNODES + 1];        // CSR row pointers (by dst)
__device__ int   g_cse[2][NEDGES];           // CSR src indices
__device__ int   g_wp[2][NNODES];            // fill cursors
__device__ int   g_bsum[2][128];             // scan block sums (raw)

// ---------------- small utility kernels ----------------
__global__ void zero_int(int* p, int n) {
    int i = blockIdx.x * blockDim.x + threadIdx.x;
    if (i < n) p[i] = 0;
}
__global__ void zero_f(float* p, int n) {
    int i = blockIdx.x * blockDim.x + threadIdx.x;
    if (i < n) p[i] = 0.0f;
}

// ---------------- CSR build (both etypes via blockIdx.y) ----------------
__global__ void count_k(const int* __restrict__ d0, const int* __restrict__ d1,
                        int* __restrict__ rpb) {
    int e = blockIdx.x * blockDim.x + threadIdx.x;
    if (e >= NEDGES) return;
    const int* dst = blockIdx.y ? d1 : d0;
    atomicAdd(&rpb[blockIdx.y * (NNODES + 1) + dst[e]], 1);
}

__global__ void scan_local(int* __restrict__ rpb, int* __restrict__ bsumb) {
    __shared__ int s[CH_SCAN];
    int* rp = rpb + blockIdx.y * (NNODES + 1);
    int* bsum = bsumb + blockIdx.y * 128;
    int tid = threadIdx.x;
    int i = blockIdx.x * CH_SCAN + tid;
    int v = (i < NNODES) ? rp[i] : 0;
    s[tid] = v;
    __syncthreads();
    for (int off = 1; off < CH_SCAN; off <<= 1) {
        int t = (tid >= off) ? s[tid - off] : 0;
        __syncthreads();
        s[tid] += t;
        __syncthreads();
    }
    if (i < NNODES) rp[i] = s[tid] - v;              // exclusive within block
    if (tid == CH_SCAN - 1) bsum[blockIdx.x] = s[tid];
}

// adds exclusive prefix of block sums (computed inline) and writes wp copy
__global__ void scan_add_wp(int* __restrict__ rpb, const int* __restrict__ bsumb,
                            int* __restrict__ wpb) {
    __shared__ int sb[128];
    int tid = threadIdx.x;
    // inline exclusive scan of the 98 raw block sums
    if (tid < 128) {
        int v = (tid < NB_SCAN) ? bsumb[blockIdx.y * 128 + tid] : 0;
        sb[tid] = v;
    }
    __syncthreads();
    // simple Hillis-Steele in shared (exclusive at the end)
    for (int off = 1; off < 128; off <<= 1) {
        int t = (tid < 128 && tid >= off) ? sb[tid - off] : 0;
        __syncthreads();
        if (tid < 128) sb[tid] += t;
        __syncthreads();
    }
    int i = blockIdx.x * blockDim.x + tid;
    int* rp = rpb + blockIdx.y * (NNODES + 1);
    int* wp = wpb + blockIdx.y * NNODES;
    if (i < NNODES) {
        int c = i / CH_SCAN;
        int pre = (c == 0) ? 0 : sb[c - 1];          // exclusive prefix
        int v = rp[i] + pre;
        rp[i] = v;
        wp[i] = v;
    }
    if (i == 0) rp[NNODES] = NEDGES;
}

__global__ void fill_k(const int* __restrict__ s0, const int* __restrict__ s1,
                       const int* __restrict__ d0, const int* __restrict__ d1,
                       int* __restrict__ wpb, int* __restrict__ csb) {
    int e = blockIdx.x * blockDim.x + threadIdx.x;
    if (e >= NEDGES) return;
    const int* src = blockIdx.y ? s1 : s0;
    const int* dst = blockIdx.y ? d1 : d0;
    int* wp = wpb + blockIdx.y * NNODES;
    int* cs = csb + blockIdx.y * NEDGES;
    int p = atomicAdd(&wp[dst[e]], 1);
    cs[p] = src[e];
}

// ---------------- fused GEMM + attention logits (fp16 Z out) ----------------
template <int K, int HF, int H>
__global__ void __launch_bounds__(256)
gemm_att(const float* __restrict__ X, const float* __restrict__ Wb,
         const float* __restrict__ alb, const float* __restrict__ arb,
         __half* __restrict__ Zb, float* __restrict__ elb, float* __restrict__ erb) {
    constexpr int TN = 8;
    constexpr int TX = HF / TN;
    constexpr int TY = 256 / TX;
    constexpr int TM = 8;
    constexpr int BM = TM * TY;
    constexpr int BK = 16;
    constexpr int RW = TX / H;

    const float* W  = Wb  + blockIdx.y * K * HF;
    const float* al = alb + blockIdx.y * HF;
    const float* ar = arb + blockIdx.y * HF;
    __half* Z = Zb  + blockIdx.y * (NNODES * 256);
    float* el = elb + blockIdx.y * (NNODES * 4);
    float* er = erb + blockIdx.y * (NNODES * 4);

    __shared__ float xs[BM][BK + 1];
    __shared__ float ws[BK][HF];

    int tid = threadIdx.x;
    int tx = tid % TX;
    int ty = tid / TX;
    int r0 = blockIdx.x * BM;

    float acc[TM][TN];
#pragma unroll
    for (int i = 0; i < TM; i++)
#pragma unroll
        for (int j = 0; j < TN; j++) acc[i][j] = 0.0f;

    for (int kb = 0; kb < K; kb += BK) {
        for (int idx = tid * 4; idx < BM * BK; idx += 1024) {
            int r = idx / BK, c = idx % BK;
            int gr = r0 + r;
            float4 v = make_float4(0.f, 0.f, 0.f, 0.f);
            if (gr < NNODES) v = *(const float4*)&X[gr * K + kb + c];
            xs[r][c] = v.x; xs[r][c + 1] = v.y; xs[r][c + 2] = v.z; xs[r][c + 3] = v.w;
        }
        for (int idx = tid; idx < BK * HF / 4; idx += 256) {
            int lin = idx * 4;
            int r = lin / HF, c = lin % HF;
            *(float4*)&ws[r][c] = *(const float4*)&W[(kb + r) * HF + c];
        }
        __syncthreads();
#pragma unroll
        for (int kk = 0; kk < BK; kk++) {
            float4 b0 = *(float4*)&ws[kk][tx * TN];
            float4 b1 = *(float4*)&ws[kk][tx * TN + 4];
            float bz[TN] = {b0.x, b0.y, b0.z, b0.w, b1.x, b1.y, b1.z, b1.w};
#pragma unroll
            for (int i = 0; i < TM; i++) {
                float a = xs[ty * TM + i][kk];
#pragma unroll
                for (int j = 0; j < TN; j++) acc[i][j] += a * bz[j];
            }
        }
        __syncthreads();
    }

    int cbase = tx * TN;
#pragma unroll
    for (int i = 0; i < TM; i++) {
        int row = r0 + ty * TM + i;
        float pl = 0.0f, pr = 0.0f;
#pragma unroll
        for (int j = 0; j < TN; j++) {
            pl += acc[i][j] * al[cbase + j];
            pr += acc[i][j] * ar[cbase + j];
        }
#pragma unroll
        for (int o = RW / 2; o > 0; o >>= 1) {
            pl += __shfl_xor_sync(0xffffffffu, pl, o);
            pr += __shfl_xor_sync(0xffffffffu, pr, o);
        }
        if (row < NNODES) {
            uint4 pack;
            __half2* ph = (__half2*)&pack;
            ph[0] = __floats2half2_rn(acc[i][0], acc[i][1]);
            ph[1] = __floats2half2_rn(acc[i][2], acc[i][3]);
            ph[2] = __floats2half2_rn(acc[i][4], acc[i][5]);
            ph[3] = __floats2half2_rn(acc[i][6], acc[i][7]);
            *(uint4*)&Z[row * HF + cbase] = pack;
            if (tx % RW == 0) {
                int h = tx / RW;
                el[row * H + h] = pl;
                er[row * H + h] = pr;
            }
        }
    }
}

// ---------------- single-pass CSR softmax + gather aggregation ----------------
__device__ __forceinline__ float lrelu(float v) {
    return (v > 0.0f) ? v : 0.2f * v;
}
__device__ __forceinline__ float2 h2f(const __half2 h) { return __half22float2(h); }

template <int HF, int H>
__global__ void __launch_bounds__(256)
gat_agg(const int* __restrict__ rp0, const int* __restrict__ cs0,
        const int* __restrict__ rp1, const int* __restrict__ cs1,
        const __half* __restrict__ z0, const __half* __restrict__ z1,
        const float* __restrict__ el0, const float* __restrict__ er0,
        const float* __restrict__ el1, const float* __restrict__ er1,
        const float* __restrict__ bia,     // (2, HF)
        const float* __restrict__ fc,      // nullptr -> c=0.5; else fc combine
        float* __restrict__ out) {
    constexpr int VEC = HF / 32;
    int w = (blockIdx.x * blockDim.x + threadIdx.x) >> 5;
    if (w >= NNODES) return;
    int lane = threadIdx.x & 31;

    float c0 = 0.5f, c1 = 0.5f;
    if (fc) { c0 = 0.5f * (fc[0] + fc[2]); c1 = 0.5f * (fc[1] + fc[3]); }

    float acc[VEC];
#pragma unroll
    for (int i = 0; i < VEC; i++) acc[i] = 0.0f;

#pragma unroll
    for (int et = 0; et < 2; et++) {
        const int* rp = et ? rp1 : rp0;
        const int* cs = et ? cs1 : cs0;
        const __half* z = et ? z1 : z0;
        const float* el = et ? el1 : el0;
        const float* er = et ? er1 : er0;
        float ce = et ? c1 : c0;

        int beg = rp[w];
        int end = rp[w + 1];
        if (beg == end) continue;

        float accE[VEC];
#pragma unroll
        for (int i = 0; i < VEC; i++) accE[i] = 0.0f;

        if constexpr (H == 1) {
            float ern = er[w];
            float den = 0.0f;
            int i = beg;
            for (; i + 4 <= end; i += 4) {
                int sa = cs[i], sb = cs[i + 1], sc = cs[i + 2], sd = cs[i + 3];
                float wa = __expf(lrelu(el[sa] + ern));
                float wb = __expf(lrelu(el[sb] + ern));
                float wc = __expf(lrelu(el[sc] + ern));
                float wd = __expf(lrelu(el[sd] + ern));
                if constexpr (HF == 128) {
                    uint2 pa = *(const uint2*)&z[sa * 128 + lane * 4];
                    uint2 pb = *(const uint2*)&z[sb * 128 + lane * 4];
                    uint2 pc = *(const uint2*)&z[sc * 128 + lane * 4];
                    uint2 pd = *(const uint2*)&z[sd * 128 + lane * 4];
                    float2 a0 = h2f(((const __half2*)&pa)[0]), a1 = h2f(((const __half2*)&pa)[1]);
                    float2 b0 = h2f(((const __half2*)&pb)[0]), b1 = h2f(((const __half2*)&pb)[1]);
                    float2 cc0 = h2f(((const __half2*)&pc)[0]), cc1 = h2f(((const __half2*)&pc)[1]);
                    float2 d0 = h2f(((const __half2*)&pd)[0]), d1 = h2f(((const __half2*)&pd)[1]);
                    accE[0] += wa * a0.x + wb * b0.x + wc * cc0.x + wd * d0.x;
                    accE[1] += wa * a0.y + wb * b0.y + wc * cc0.y + wd * d0.y;
                    accE[2] += wa * a1.x + wb * b1.x + wc * cc1.x + wd * d1.x;
                    accE[3] += wa * a1.y + wb * b1.y + wc * cc1.y + wd * d1.y;
                } else {  // HF == 64
                    float2 a0 = h2f(*(const __half2*)&z[sa * 64 + lane * 2]);
                    float2 b0 = h2f(*(const __half2*)&z[sb * 64 + lane * 2]);
                    float2 cc0 = h2f(*(const __half2*)&z[sc * 64 + lane * 2]);
                    float2 d0 = h2f(*(const __half2*)&z[sd * 64 + lane * 2]);
                    accE[0] += wa * a0.x + wb * b0.x + wc * cc0.x + wd * d0.x;
                    accE[1] += wa * a0.y + wb * b0.y + wc * cc0.y + wd * d0.y;
                }
                den += wa + wb + wc + wd;
            }
            for (; i < end; i++) {
                int s = cs[i];
                float wt = __expf(lrelu(el[s] + ern));
                den += wt;
                if constexpr (HF == 128) {
                    uint2 p = *(const uint2*)&z[s * 128 + lane * 4];
                    float2 f0 = h2f(((const __half2*)&p)[0]);
                    float2 f1 = h2f(((const __half2*)&p)[1]);
                    accE[0] += wt * f0.x; accE[1] += wt * f0.y;
                    accE[2] += wt * f1.x; accE[3] += wt * f1.y;
                } else {
                    float2 f0 = h2f(*(const __half2*)&z[s * 64 + lane * 2]);
                    accE[0] += wt * f0.x; accE[1] += wt * f0.y;
                }
            }
            float sc1 = ce / fmaxf(den, 1e-30f);
#pragma unroll
            for (int j = 0; j < VEC; j++) acc[j] += accE[j] * sc1;
        } else {  // H == 4, HF == 256
            int h0 = lane >> 4;
            int h1 = 2 + (lane >> 4);
            float ern0 = er[w * 4 + h0];
            float ern1 = er[w * 4 + h1];
            float den0 = 0.0f, den1 = 0.0f;
            int i = beg;
            for (; i + 2 <= end; i += 2) {
                int sa = cs[i], sb = cs[i + 1];
                float wa0 = __expf(lrelu(el[sa * 4 + h0] + ern0));
                float wa1 = __expf(lrelu(el[sa * 4 + h1] + ern1));
                float wb0 = __expf(lrelu(el[sb * 4 + h0] + ern0));
                float wb1 = __expf(lrelu(el[sb * 4 + h1] + ern1));
                uint2 pa0 = *(const uint2*)&z[sa * 256 + lane * 4];
                uint2 pa1 = *(const uint2*)&z[sa * 256 + 128 + lane * 4];
                uint2 pb0 = *(const uint2*)&z[sb * 256 + lane * 4];
                uint2 pb1 = *(const uint2*)&z[sb * 256 + 128 + lane * 4];
                float2 a00 = h2f(((const __half2*)&pa0)[0]), a01 = h2f(((const __half2*)&pa0)[1]);
                float2 a10 = h2f(((const __half2*)&pa1)[0]), a11 = h2f(((const __half2*)&pa1)[1]);
                float2 b00 = h2f(((const __half2*)&pb0)[0]), b01 = h2f(((const __half2*)&pb0)[1]);
                float2 b10 = h2f(((const __half2*)&pb1)[0]), b11 = h2f(((const __half2*)&pb1)[1]);
                accE[0] += wa0 * a00.x + wb0 * b00.x;
                accE[1] += wa0 * a00.y + wb0 * b00.y;
                accE[2] += wa0 * a01.x + wb0 * b01.x;
                accE[3] += wa0 * a01.y + wb0 * b01.y;
                accE[4] += wa1 * a10.x + wb1 * b10.x;
                accE[5] += wa1 * a10.y + wb1 * b10.y;
                accE[6] += wa1 * a11.x + wb1 * b11.x;
                accE[7] += wa1 * a11.y + wb1 * b11.y;
                den0 += wa0 + wb0;
                den1 += wa1 + wb1;
            }
            for (; i < end; i++) {
                int s = cs[i];
                float w0 = __expf(lrelu(el[s * 4 + h0] + ern0));
                float w1 = __expf(lrelu(el[s * 4 + h1] + ern1));
                uint2 p0 = *(const uint2*)&z[s * 256 + lane * 4];
                uint2 p1 = *(const uint2*)&z[s * 256 + 128 + lane * 4];
                float2 f00 = h2f(((const __half2*)&p0)[0]), f01 = h2f(((const __half2*)&p0)[1]);
                float2 f10 = h2f(((const __half2*)&p1)[0]), f11 = h2f(((const __half2*)&p1)[1]);
                accE[0] += w0 * f00.x; accE[1] += w0 * f00.y;
                accE[2] += w0 * f01.x; accE[3] += w0 * f01.y;
                accE[4] += w1 * f10.x; accE[5] += w1 * f10.y;
                accE[6] += w1 * f11.x; accE[7] += w1 * f11.y;
                den0 += w0;
                den1 += w1;
            }
            float s0 = ce / fmaxf(den0, 1e-30f);
            float s1 = ce / fmaxf(den1, 1e-30f);
#pragma unroll
            for (int j = 0; j < 4; j++) acc[j] += accE[j] * s0;
#pragma unroll
            for (int j = 4; j < 8; j++) acc[j] += accE[j] * s1;
        }
    }

    // write output with combined bias
    if constexpr (HF == 64) {
        int f = lane * 2;
        float2 o;
        o.x = acc[0] + c0 * bia[f] + c1 * bia[64 + f];
        o.y = acc[1] + c0 * bia[f + 1] + c1 * bia[64 + f + 1];
        *(float2*)&out[w * 64 + f] = o;
    } else if constexpr (HF == 128) {
        int f = lane * 4;
        float4 o;
        o.x = acc[0] + c0 * bia[f + 0] + c1 * bia[128 + f + 0];
        o.y = acc[1] + c0 * bia[f + 1] + c1 * bia[128 + f + 1];
        o.z = acc[2] + c0 * bia[f + 2] + c1 * bia[128 + f + 2];
        o.w = acc[3] + c0 * bia[f + 3] + c1 * bia[128 + f + 3];
        *(float4*)&out[w * 128 + f] = o;
    } else {
        int f = lane * 4;
        float4 o0, o1;
        o0.x = acc[0] + c0 * bia[f + 0] + c1 * bia[256 + f + 0];
        o0.y = acc[1] + c0 * bia[f + 1] + c1 * bia[256 + f + 1];
        o0.z = acc[2] + c0 * bia[f + 2] + c1 * bia[256 + f + 2];
        o0.w = acc[3] + c0 * bia[f + 3] + c1 * bia[256 + f + 3];
        o1.x = acc[4] + c0 * bia[128 + f + 0] + c1 * bia[256 + 128 + f + 0];
        o1.y = acc[5] + c0 * bia[128 + f + 1] + c1 * bia[256 + 128 + f + 1];
        o1.z = acc[6] + c0 * bia[128 + f + 2] + c1 * bia[256 + 128 + f + 2];
        o1.w = acc[7] + c0 * bia[128 + f + 3] + c1 * bia[256 + 128 + f + 3];
        *(float4*)&out[w * 256 + f] = o0;
        *(float4*)&out[w * 256 + 128 + f] = o1;
    }
}

// ---------------- final centering ----------------
__global__ void colsum_kernel(const float* __restrict__ out, float* __restrict__ cs) {
    const int RPB = 64;
    int c = threadIdx.x;
    int r0 = blockIdx.x * RPB;
    int r1 = r0 + RPB; if (r1 > NNODES) r1 = NNODES;
    float acc = 0.0f;
    for (int r = r0; r < r1; r++) acc += out[r * 256 + c];
    atomicAdd(&cs[c], acc);
}

__global__ void center_kernel(float* __restrict__ out, const float* __restrict__ cs) {
    int i = blockIdx.x * blockDim.x + threadIdx.x;
    if (i < NNODES * 256) out[i] -= cs[i & 255] * (1.0f / NNODES);
}

// ---------------- orchestration ----------------
extern "C" void kernel_launch(void* const* d_in, const int* in_sizes, int n_in,
                              void* d_out, int out_size) {
    const float* x   = (const float*)d_in[0];
    const int* src0 = (const int*)d_in[1];
    const int* dst0 = (const int*)d_in[2];
    const int* src1 = (const int*)d_in[3];
    const int* dst1 = (const int*)d_in[4];
    const float* W1  = (const float*)d_in[5];
    const float* al1 = (const float*)d_in[6];
    const float* ar1 = (const float*)d_in[7];
    const float* b1  = (const float*)d_in[8];
    const float* W2  = (const float*)d_in[9];
    const float* al2 = (const float*)d_in[10];
    const float* ar2 = (const float*)d_in[11];
    const float* b2  = (const float*)d_in[12];
    const float* Wm  = (const float*)d_in[13];
    const float* alm = (const float*)d_in[14];
    const float* arm = (const float*)d_in[15];
    const float* bm  = (const float*)d_in[16];
    const float* fc  = (const float*)d_in[17];
    float* out = (float*)d_out;

    __half* zb;
    float *h1, *h2, *elb, *erb, *csum;
    int *rpb, *cseb, *wpb, *bsumb;
    cudaGetSymbolAddress((void**)&zb,    g_z);
    cudaGetSymbolAddress((void**)&h1,    g_h1);
    cudaGetSymbolAddress((void**)&h2,    g_h2);
    cudaGetSymbolAddress((void**)&elb,   g_el);
    cudaGetSymbolAddress((void**)&erb,   g_er);
    cudaGetSymbolAddress((void**)&csum,  g_colsum);
    cudaGetSymbolAddress((void**)&rpb,   g_rp);
    cudaGetSymbolAddress((void**)&cseb,  g_cse);
    cudaGetSymbolAddress((void**)&wpb,   g_wp);
    cudaGetSymbolAddress((void**)&bsumb, g_bsum);

    int* rp[2]  = {rpb, rpb + (NNODES + 1)};
    int* cse[2] = {cseb, cseb + NEDGES};
    __half* z[2] = {zb, zb + NNODES * 256};
    float* el[2] = {elb, elb + NNODES * 4};
    float* er[2] = {erb, erb + NNODES * 4};

    const int EG = (NEDGES + 255) / 256;
    const int NG = (NNODES + 255) / 256;
    const int AGG_BLOCKS = (NNODES * 32 + 255) / 256;

    // ---------------- CSR build (by dst), both etypes per launch -----------
    zero_int<<<(2 * (NNODES + 1) + 255) / 256, 256>>>(rpb, 2 * (NNODES + 1));
    count_k<<<dim3(EG, 2), 256>>>(dst0, dst1, rpb);
    scan_local<<<dim3(NB_SCAN, 2), CH_SCAN>>>(rpb, bsumb);
    scan_add_wp<<<dim3(NG, 2), 256>>>(rpb, bsumb, wpb);
    fill_k<<<dim3(EG, 2), 256>>>(src0, src1, dst0, dst1, wpb, cseb);

    // ---------------- layer 1: x(128) -> h1(128), H=1 ----------------
    gemm_att<128, 128, 1><<<dim3((NNODES + 127) / 128, 2), 256>>>(
        x, W1, al1, ar1, zb, elb, erb);
    gat_agg<128, 1><<<AGG_BLOCKS, 256>>>(
        rp[0], cse[0], rp[1], cse[1], z[0], z[1],
        el[0], er[0], el[1], er[1], b1, nullptr, h1);

    // ---------------- layer 2: h1(128) -> h2(64), H=1, fc combine -------
    gemm_att<128, 64, 1><<<dim3((NNODES + 255) / 256, 2), 256>>>(
        h1, W2, al2, ar2, zb, elb, erb);
    gat_agg<64, 1><<<AGG_BLOCKS, 256>>>(
        rp[0], cse[0], rp[1], cse[1], z[0], z[1],
        el[0], er[0], el[1], er[1], b2, fc, h2);

    // ---------------- layer MH: h2(64) -> out(4x64), H=4 ----------------
    gemm_att<64, 256, 4><<<dim3((NNODES + 63) / 64, 2), 256>>>(
        h2, Wm, alm, arm, zb, elb, erb);
    gat_agg<256, 4><<<AGG_BLOCKS, 256>>>(
        rp[0], cse[0], rp[1], cse[1], z[0], z[1],
        el[0], er[0], el[1], er[1], bm, nullptr, out);

    // ---------------- final per-column mean centering -------------------
    zero_f<<<1, 256>>>(csum, 256);
    colsum_kernel<<<(NNODES + 63) / 64, 256>>>(out, csum);
    center_kernel<<<(NNODES * 256 + 255) / 256, 256>>>(out, csum);
}

// round 5
// speedup vs baseline: 4.3932x; 1.0635x over previous
#include <cuda_runtime.h>
#include <cuda_fp16.h>
#include <math.h>

#define NNODES 50000
#define NEDGES 800000
#define CH_SCAN 512
#define NB_SCAN ((NNODES + CH_SCAN - 1) / CH_SCAN)   // 98

// ---------------- scratch (static device globals; no allocations) ----------
__device__ __half g_z[2 * NNODES * 256];     // fp16 per-etype GEMM output
__device__ float g_h1[NNODES * 128];
__device__ float g_h2[NNODES * 64];
__device__ float g_el[2 * NNODES * 4];
__device__ float g_er[2 * NNODES * 4];
__device__ float g_colsum[256];
__device__ int   g_rp[2][NNODES + 1];        // CSR row pointers (by dst)
__device__ int   g_cse[2][NEDGES];           // CSR src indices
__device__ int   g_wp[2][NNODES];            // fill cursors
__device__ int   g_bsum[2][128];             // scan block sums (raw)

// ---------------- small utility kernels ----------------
__global__ void zero_int(int* p, int n) {
    int i = blockIdx.x * blockDim.x + threadIdx.x;
    if (i < n) p[i] = 0;
}
__global__ void zero_f(float* p, int n) {
    int i = blockIdx.x * blockDim.x + threadIdx.x;
    if (i < n) p[i] = 0.0f;
}

// ---------------- CSR build pieces ----------------
__global__ void scan_local(int* __restrict__ rpb, int* __restrict__ bsumb) {
    __shared__ int s[CH_SCAN];
    int* rp = rpb + blockIdx.y * (NNODES + 1);
    int* bsum = bsumb + blockIdx.y * 128;
    int tid = threadIdx.x;
    int i = blockIdx.x * CH_SCAN + tid;
    int v = (i < NNODES) ? rp[i] : 0;
    s[tid] = v;
    __syncthreads();
    for (int off = 1; off < CH_SCAN; off <<= 1) {
        int t = (tid >= off) ? s[tid - off] : 0;
        __syncthreads();
        s[tid] += t;
        __syncthreads();
    }
    if (i < NNODES) rp[i] = s[tid] - v;              // exclusive within block
    if (tid == CH_SCAN - 1) bsum[blockIdx.x] = s[tid];
}

__global__ void scan_add_wp(int* __restrict__ rpb, const int* __restrict__ bsumb,
                            int* __restrict__ wpb) {
    __shared__ int sb[128];
    int tid = threadIdx.x;
    if (tid < 128) {
        int v = (tid < NB_SCAN) ? bsumb[blockIdx.y * 128 + tid] : 0;
        sb[tid] = v;
    }
    __syncthreads();
    for (int off = 1; off < 128; off <<= 1) {
        int t = (tid < 128 && tid >= off) ? sb[tid - off] : 0;
        __syncthreads();
        if (tid < 128) sb[tid] += t;
        __syncthreads();
    }
    int i = blockIdx.x * blockDim.x + tid;
    int* rp = rpb + blockIdx.y * (NNODES + 1);
    int* wp = wpb + blockIdx.y * NNODES;
    if (i < NNODES) {
        int c = i / CH_SCAN;
        int pre = (c == 0) ? 0 : sb[c - 1];
        int v = rp[i] + pre;
        rp[i] = v;
        wp[i] = v;
    }
    if (i == 0) rp[NNODES] = NEDGES;
}

__global__ void fill_k(const int* __restrict__ s0, const int* __restrict__ s1,
                       const int* __restrict__ d0, const int* __restrict__ d1,
                       int* __restrict__ wpb, int* __restrict__ csb) {
    int e = blockIdx.x * blockDim.x + threadIdx.x;
    if (e >= NEDGES) return;
    const int* src = blockIdx.y ? s1 : s0;
    const int* dst = blockIdx.y ? d1 : d0;
    int* wp = wpb + blockIdx.y * NNODES;
    int* cs = csb + blockIdx.y * NEDGES;
    int p = atomicAdd(&wp[dst[e]], 1);
    cs[p] = src[e];
}

// ---------------- GEMM body (transposed X tile, float4 LDS) ----------------
template <int K, int HF, int H>
__device__ __forceinline__ void
gemm_body(int bx, int by,
          const float* __restrict__ X, const float* __restrict__ Wb,
          const float* __restrict__ alb, const float* __restrict__ arb,
          __half* __restrict__ Zb, float* __restrict__ elb, float* __restrict__ erb) {
    constexpr int TN = 8, TM = 8, BK = 16;
    constexpr int TX = HF / TN;
    constexpr int TY = 256 / TX;
    constexpr int BM = TM * TY;
    constexpr int BMP = BM + 4;                // pad: keeps 16B alignment, kills conflicts
    constexpr int RW = TX / H;

    __shared__ float xs[BK][BMP];              // transposed X tile
    __shared__ float ws[BK][HF];

    const float* W  = Wb  + by * K * HF;
    const float* al = alb + by * HF;
    const float* ar = arb + by * HF;
    __half* Z = Zb  + by * (NNODES * 256);
    float* el = elb + by * (NNODES * 4);
    float* er = erb + by * (NNODES * 4);

    int tid = threadIdx.x;
    int tx = tid % TX;
    int ty = tid / TX;
    int r0 = bx * BM;

    float acc[TM][TN];
#pragma unroll
    for (int i = 0; i < TM; i++)
#pragma unroll
        for (int j = 0; j < TN; j++) acc[i][j] = 0.0f;

    for (int kb = 0; kb < K; kb += BK) {
        // X tile: load float4 row-major, store transposed
#pragma unroll
        for (int idx = tid; idx < BM * BK / 4; idx += 256) {
            int lin = idx * 4;
            int r = lin / BK, c = lin % BK;
            int gr = r0 + r;
            float4 v = make_float4(0.f, 0.f, 0.f, 0.f);
            if (gr < NNODES) v = *(const float4*)&X[gr * K + kb + c];
            xs[c][r] = v.x; xs[c + 1][r] = v.y; xs[c + 2][r] = v.z; xs[c + 3][r] = v.w;
        }
        // W tile
#pragma unroll
        for (int idx = tid; idx < BK * HF / 4; idx += 256) {
            int lin = idx * 4;
            int r = lin / HF, c = lin % HF;
            *(float4*)&ws[r][c] = *(const float4*)&W[(kb + r) * HF + c];
        }
        __syncthreads();
#pragma unroll
        for (int kk = 0; kk < BK; kk++) {
            float4 a0 = *(const float4*)&xs[kk][ty * 8];
            float4 a1 = *(const float4*)&xs[kk][ty * 8 + 4];
            float4 b0 = *(const float4*)&ws[kk][tx * 8];
            float4 b1 = *(const float4*)&ws[kk][tx * 8 + 4];
            float av[TM] = {a0.x, a0.y, a0.z, a0.w, a1.x, a1.y, a1.z, a1.w};
            float bv[TN] = {b0.x, b0.y, b0.z, b0.w, b1.x, b1.y, b1.z, b1.w};
#pragma unroll
            for (int i = 0; i < TM; i++)
#pragma unroll
                for (int j = 0; j < TN; j++) acc[i][j] += av[i] * bv[j];
        }
        __syncthreads();
    }

    int cbase = tx * TN;
#pragma unroll
    for (int i = 0; i < TM; i++) {
        int row = r0 + ty * TM + i;
        float pl = 0.0f, pr = 0.0f;
#pragma unroll
        for (int j = 0; j < TN; j++) {
            pl += acc[i][j] * al[cbase + j];
            pr += acc[i][j] * ar[cbase + j];
        }
#pragma unroll
        for (int o = RW / 2; o > 0; o >>= 1) {
            pl += __shfl_xor_sync(0xffffffffu, pl, o);
            pr += __shfl_xor_sync(0xffffffffu, pr, o);
        }
        if (row < NNODES) {
            uint4 pack;
            __half2* ph = (__half2*)&pack;
            ph[0] = __floats2half2_rn(acc[i][0], acc[i][1]);
            ph[1] = __floats2half2_rn(acc[i][2], acc[i][3]);
            ph[2] = __floats2half2_rn(acc[i][4], acc[i][5]);
            ph[3] = __floats2half2_rn(acc[i][6], acc[i][7]);
            *(uint4*)&Z[row * HF + cbase] = pack;
            if (tx % RW == 0) {
                int h = tx / RW;
                el[row * H + h] = pl;
                er[row * H + h] = pr;
            }
        }
    }
}

template <int K, int HF, int H>
__global__ void __launch_bounds__(256)
gemm_att(const float* __restrict__ X, const float* __restrict__ Wb,
         const float* __restrict__ alb, const float* __restrict__ arb,
         __half* __restrict__ Zb, float* __restrict__ elb, float* __restrict__ erb) {
    gemm_body<K, HF, H>(blockIdx.x, blockIdx.y, X, Wb, alb, arb, Zb, elb, erb);
}

// layer-1 GEMM fused with independent CSR edge counting (overlap on one wave)
__global__ void __launch_bounds__(256)
gemm1_count(const float* __restrict__ X, const float* __restrict__ Wb,
            const float* __restrict__ alb, const float* __restrict__ arb,
            __half* __restrict__ Zb, float* __restrict__ elb, float* __restrict__ erb,
            const int* __restrict__ d0, const int* __restrict__ d1,
            int* __restrict__ rpb, int gemmX, int countBlocks) {
    if ((int)blockIdx.x < gemmX) {
        gemm_body<128, 128, 1>(blockIdx.x, blockIdx.y, X, Wb, alb, arb, Zb, elb, erb);
    } else {
        int cb = blockIdx.x - gemmX;
        const int* dst = blockIdx.y ? d1 : d0;
        int* cnt = rpb + blockIdx.y * (NNODES + 1);
        for (int e = cb * 256 + threadIdx.x; e < NEDGES; e += countBlocks * 256)
            atomicAdd(&cnt[dst[e]], 1);
    }
}

// ---------------- single-pass CSR softmax + gather aggregation ----------------
__device__ __forceinline__ float lrelu(float v) {
    return (v > 0.0f) ? v : 0.2f * v;
}
__device__ __forceinline__ float2 h2f(const __half2 h) { return __half22float2(h); }

template <int HF, int H>
__global__ void __launch_bounds__(256)
gat_agg(const int* __restrict__ rp0, const int* __restrict__ cs0,
        const int* __restrict__ rp1, const int* __restrict__ cs1,
        const __half* __restrict__ z0, const __half* __restrict__ z1,
        const float* __restrict__ el0, const float* __restrict__ er0,
        const float* __restrict__ el1, const float* __restrict__ er1,
        const float* __restrict__ bia,     // (2, HF)
        const float* __restrict__ fc,      // nullptr -> c=0.5; else fc combine
        float* __restrict__ out) {
    constexpr int VEC = HF / 32;
    int w = (blockIdx.x * blockDim.x + threadIdx.x) >> 5;
    if (w >= NNODES) return;
    int lane = threadIdx.x & 31;

    float c0 = 0.5f, c1 = 0.5f;
    if (fc) { c0 = 0.5f * (fc[0] + fc[2]); c1 = 0.5f * (fc[1] + fc[3]); }

    float acc[VEC];
#pragma unroll
    for (int i = 0; i < VEC; i++) acc[i] = 0.0f;

#pragma unroll
    for (int et = 0; et < 2; et++) {
        const int* rp = et ? rp1 : rp0;
        const int* cs = et ? cs1 : cs0;
        const __half* z = et ? z1 : z0;
        const float* el = et ? el1 : el0;
        const float* er = et ? er1 : er0;
        float ce = et ? c1 : c0;

        int beg = rp[w];
        int end = rp[w + 1];
        if (beg == end) continue;

        float accE[VEC];
#pragma unroll
        for (int i = 0; i < VEC; i++) accE[i] = 0.0f;

        if constexpr (H == 1) {
            float ern = er[w];
            float den = 0.0f;
            int i = beg;
            for (; i + 4 <= end; i += 4) {
                int sa = cs[i], sb = cs[i + 1], sc = cs[i + 2], sd = cs[i + 3];
                float wa = __expf(lrelu(el[sa] + ern));
                float wb = __expf(lrelu(el[sb] + ern));
                float wc = __expf(lrelu(el[sc] + ern));
                float wd = __expf(lrelu(el[sd] + ern));
                if constexpr (HF == 128) {
                    uint2 pa = *(const uint2*)&z[sa * 128 + lane * 4];
                    uint2 pb = *(const uint2*)&z[sb * 128 + lane * 4];
                    uint2 pc = *(const uint2*)&z[sc * 128 + lane * 4];
                    uint2 pd = *(const uint2*)&z[sd * 128 + lane * 4];
                    float2 a0 = h2f(((const __half2*)&pa)[0]), a1 = h2f(((const __half2*)&pa)[1]);
                    float2 b0 = h2f(((const __half2*)&pb)[0]), b1 = h2f(((const __half2*)&pb)[1]);
                    float2 cc0 = h2f(((const __half2*)&pc)[0]), cc1 = h2f(((const __half2*)&pc)[1]);
                    float2 d0 = h2f(((const __half2*)&pd)[0]), d1 = h2f(((const __half2*)&pd)[1]);
                    accE[0] += wa * a0.x + wb * b0.x + wc * cc0.x + wd * d0.x;
                    accE[1] += wa * a0.y + wb * b0.y + wc * cc0.y + wd * d0.y;
                    accE[2] += wa * a1.x + wb * b1.x + wc * cc1.x + wd * d1.x;
                    accE[3] += wa * a1.y + wb * b1.y + wc * cc1.y + wd * d1.y;
                } else {  // HF == 64
                    float2 a0 = h2f(*(const __half2*)&z[sa * 64 + lane * 2]);
                    float2 b0 = h2f(*(const __half2*)&z[sb * 64 + lane * 2]);
                    float2 cc0 = h2f(*(const __half2*)&z[sc * 64 + lane * 2]);
                    float2 d0 = h2f(*(const __half2*)&z[sd * 64 + lane * 2]);
                    accE[0] += wa * a0.x + wb * b0.x + wc * cc0.x + wd * d0.x;
                    accE[1] += wa * a0.y + wb * b0.y + wc * cc0.y + wd * d0.y;
                }
                den += wa + wb + wc + wd;
            }
            for (; i < end; i++) {
                int s = cs[i];
                float wt = __expf(lrelu(el[s] + ern));
                den += wt;
                if constexpr (HF == 128) {
                    uint2 p = *(const uint2*)&z[s * 128 + lane * 4];
                    float2 f0 = h2f(((const __half2*)&p)[0]);
                    float2 f1 = h2f(((const __half2*)&p)[1]);
                    accE[0] += wt * f0.x; accE[1] += wt * f0.y;
                    accE[2] += wt * f1.x; accE[3] += wt * f1.y;
                } else {
                    float2 f0 = h2f(*(const __half2*)&z[s * 64 + lane * 2]);
                    accE[0] += wt * f0.x; accE[1] += wt * f0.y;
                }
            }
            float sc1 = ce / fmaxf(den, 1e-30f);
#pragma unroll
            for (int j = 0; j < VEC; j++) acc[j] += accE[j] * sc1;
        } else {  // H == 4, HF == 256
            int h0 = lane >> 4;
            int h1 = 2 + (lane >> 4);
            float ern0 = er[w * 4 + h0];
            float ern1 = er[w * 4 + h1];
            float den0 = 0.0f, den1 = 0.0f;
            int i = beg;
            for (; i + 2 <= end; i += 2) {
                int sa = cs[i], sb = cs[i + 1];
                float wa0 = __expf(lrelu(el[sa * 4 + h0] + ern0));
                float wa1 = __expf(lrelu(el[sa * 4 + h1] + ern1));
                float wb0 = __expf(lrelu(el[sb * 4 + h0] + ern0));
                float wb1 = __expf(lrelu(el[sb * 4 + h1] + ern1));
                uint2 pa0 = *(const uint2*)&z[sa * 256 + lane * 4];
                uint2 pa1 = *(const uint2*)&z[sa * 256 + 128 + lane * 4];
                uint2 pb0 = *(const uint2*)&z[sb * 256 + lane * 4];
                uint2 pb1 = *(const uint2*)&z[sb * 256 + 128 + lane * 4];
                float2 a00 = h2f(((const __half2*)&pa0)[0]), a01 = h2f(((const __half2*)&pa0)[1]);
                float2 a10 = h2f(((const __half2*)&pa1)[0]), a11 = h2f(((const __half2*)&pa1)[1]);
                float2 b00 = h2f(((const __half2*)&pb0)[0]), b01 = h2f(((const __half2*)&pb0)[1]);
                float2 b10 = h2f(((const __half2*)&pb1)[0]), b11 = h2f(((const __half2*)&pb1)[1]);
                accE[0] += wa0 * a00.x + wb0 * b00.x;
                accE[1] += wa0 * a00.y + wb0 * b00.y;
                accE[2] += wa0 * a01.x + wb0 * b01.x;
                accE[3] += wa0 * a01.y + wb0 * b01.y;
                accE[4] += wa1 * a10.x + wb1 * b10.x;
                accE[5] += wa1 * a10.y + wb1 * b10.y;
                accE[6] += wa1 * a11.x + wb1 * b11.x;
                accE[7] += wa1 * a11.y + wb1 * b11.y;
                den0 += wa0 + wb0;
                den1 += wa1 + wb1;
            }
            for (; i < end; i++) {
                int s = cs[i];
                float w0 = __expf(lrelu(el[s * 4 + h0] + ern0));
                float w1 = __expf(lrelu(el[s * 4 + h1] + ern1));
                uint2 p0 = *(const uint2*)&z[s * 256 + lane * 4];
                uint2 p1 = *(const uint2*)&z[s * 256 + 128 + lane * 4];
                float2 f00 = h2f(((const __half2*)&p0)[0]), f01 = h2f(((const __half2*)&p0)[1]);
                float2 f10 = h2f(((const __half2*)&p1)[0]), f11 = h2f(((const __half2*)&p1)[1]);
                accE[0] += w0 * f00.x; accE[1] += w0 * f00.y;
                accE[2] += w0 * f01.x; accE[3] += w0 * f01.y;
                accE[4] += w1 * f10.x; accE[5] += w1 * f10.y;
                accE[6] += w1 * f11.x; accE[7] += w1 * f11.y;
                den0 += w0;
                den1 += w1;
            }
            float s0 = ce / fmaxf(den0, 1e-30f);
            float s1 = ce / fmaxf(den1, 1e-30f);
#pragma unroll
            for (int j = 0; j < 4; j++) acc[j] += accE[j] * s0;
#pragma unroll
            for (int j = 4; j < 8; j++) acc[j] += accE[j] * s1;
        }
    }

    // write output with combined bias
    if constexpr (HF == 64) {
        int f = lane * 2;
        float2 o;
        o.x = acc[0] + c0 * bia[f] + c1 * bia[64 + f];
        o.y = acc[1] + c0 * bia[f + 1] + c1 * bia[64 + f + 1];
        *(float2*)&out[w * 64 + f] = o;
    } else if constexpr (HF == 128) {
        int f = lane * 4;
        float4 o;
        o.x = acc[0] + c0 * bia[f + 0] + c1 * bia[128 + f + 0];
        o.y = acc[1] + c0 * bia[f + 1] + c1 * bia[128 + f + 1];
        o.z = acc[2] + c0 * bia[f + 2] + c1 * bia[128 + f + 2];
        o.w = acc[3] + c0 * bia[f + 3] + c1 * bia[128 + f + 3];
        *(float4*)&out[w * 128 + f] = o;
    } else {
        int f = lane * 4;
        float4 o0, o1;
        o0.x = acc[0] + c0 * bia[f + 0] + c1 * bia[256 + f + 0];
        o0.y = acc[1] + c0 * bia[f + 1] + c1 * bia[256 + f + 1];
        o0.z = acc[2] + c0 * bia[f + 2] + c1 * bia[256 + f + 2];
        o0.w = acc[3] + c0 * bia[f + 3] + c1 * bia[256 + f + 3];
        o1.x = acc[4] + c0 * bia[128 + f + 0] + c1 * bia[256 + 128 + f + 0];
        o1.y = acc[5] + c0 * bia[128 + f + 1] + c1 * bia[256 + 128 + f + 1];
        o1.z = acc[6] + c0 * bia[128 + f + 2] + c1 * bia[256 + 128 + f + 2];
        o1.w = acc[7] + c0 * bia[128 + f + 3] + c1 * bia[256 + 128 + f + 3];
        *(float4*)&out[w * 256 + f] = o0;
        *(float4*)&out[w * 256 + 128 + f] = o1;
    }
}

// ---------------- final centering ----------------
__global__ void colsum_kernel(const float* __restrict__ out, float* __restrict__ cs) {
    const int RPB = 64;
    int c = threadIdx.x;
    int r0 = blockIdx.x * RPB;
    int r1 = r0 + RPB; if (r1 > NNODES) r1 = NNODES;
    float acc = 0.0f;
    for (int r = r0; r < r1; r++) acc += out[r * 256 + c];
    atomicAdd(&cs[c], acc);
}

__global__ void center_kernel(float* __restrict__ out, const float* __restrict__ cs) {
    int i = blockIdx.x * blockDim.x + threadIdx.x;
    if (i < NNODES * 256) out[i] -= cs[i & 255] * (1.0f / NNODES);
}

// ---------------- orchestration ----------------
extern "C" void kernel_launch(void* const* d_in, const int* in_sizes, int n_in,
                              void* d_out, int out_size) {
    const float* x   = (const float*)d_in[0];
    const int* src0 = (const int*)d_in[1];
    const int* dst0 = (const int*)d_in[2];
    const int* src1 = (const int*)d_in[3];
    const int* dst1 = (const int*)d_in[4];
    const float* W1  = (const float*)d_in[5];
    const float* al1 = (const float*)d_in[6];
    const float* ar1 = (const float*)d_in[7];
    const float* b1  = (const float*)d_in[8];
    const float* W2  = (const float*)d_in[9];
    const float* al2 = (const float*)d_in[10];
    const float* ar2 = (const float*)d_in[11];
    const float* b2  = (const float*)d_in[12];
    const float* Wm  = (const float*)d_in[13];
    const float* alm = (const float*)d_in[14];
    const float* arm = (const float*)d_in[15];
    const float* bm  = (const float*)d_in[16];
    const float* fc  = (const float*)d_in[17];
    float* out = (float*)d_out;

    __half* zb;
    float *h1, *h2, *elb, *erb, *csum;
    int *rpb, *cseb, *wpb, *bsumb;
    cudaGetSymbolAddress((void**)&zb,    g_z);
    cudaGetSymbolAddress((void**)&h1,    g_h1);
    cudaGetSymbolAddress((void**)&h2,    g_h2);
    cudaGetSymbolAddress((void**)&elb,   g_el);
    cudaGetSymbolAddress((void**)&erb,   g_er);
    cudaGetSymbolAddress((void**)&csum,  g_colsum);
    cudaGetSymbolAddress((void**)&rpb,   g_rp);
    cudaGetSymbolAddress((void**)&cseb,  g_cse);
    cudaGetSymbolAddress((void**)&wpb,   g_wp);
    cudaGetSymbolAddress((void**)&bsumb, g_bsum);

    int* rp[2]  = {rpb, rpb + (NNODES + 1)};
    int* cse[2] = {cseb, cseb + NEDGES};
    __half* z[2] = {zb, zb + NNODES * 256};
    float* el[2] = {elb, elb + NNODES * 4};
    float* er[2] = {erb, erb + NNODES * 4};

    const int EG = (NEDGES + 255) / 256;
    const int AGG_BLOCKS = (NNODES * 32 + 255) / 256;

    // ---------------- zero counters, then fused GEMM1 + edge count ---------
    zero_int<<<(2 * (NNODES + 1) + 255) / 256, 256>>>(rpb, 2 * (NNODES + 1));

    const int GEMM1_X = (NNODES + 127) / 128;        // BM=128 -> 391
    const int COUNT_B = 256;                         // grid-stride count blocks/etype
    gemm1_count<<<dim3(GEMM1_X + COUNT_B, 2), 256>>>(
        x, W1, al1, ar1, zb, elb, erb, dst0, dst1, rpb, GEMM1_X, COUNT_B);

    // ---------------- finish CSR build ----------------
    scan_local<<<dim3(NB_SCAN, 2), CH_SCAN>>>(rpb, bsumb);
    scan_add_wp<<<dim3((NNODES + 255) / 256, 2), 256>>>(rpb, bsumb, wpb);
    fill_k<<<dim3(EG, 2), 256>>>(src0, src1, dst0, dst1, wpb, cseb);

    // ---------------- layer 1 aggregation ----------------
    gat_agg<128, 1><<<AGG_BLOCKS, 256>>>(
        rp[0], cse[0], rp[1], cse[1], z[0], z[1],
        el[0], er[0], el[1], er[1], b1, nullptr, h1);

    // ---------------- layer 2: h1(128) -> h2(64), H=1, fc combine -------
    gemm_att<128, 64, 1><<<dim3((NNODES + 255) / 256, 2), 256>>>(
        h1, W2, al2, ar2, zb, elb, erb);
    gat_agg<64, 1><<<AGG_BLOCKS, 256>>>(
        rp[0], cse[0], rp[1], cse[1], z[0], z[1],
        el[0], er[0], el[1], er[1], b2, fc, h2);

    // ---------------- layer MH: h2(64) -> out(4x64), H=4 ----------------
    gemm_att<64, 256, 4><<<dim3((NNODES + 63) / 64, 2), 256>>>(
        h2, Wm, alm, arm, zb, elb, erb);
    gat_agg<256, 4><<<AGG_BLOCKS, 256>>>(
        rp[0], cse[0], rp[1], cse[1], z[0], z[1],
        el[0], er[0], el[1], er[1], bm, nullptr, out);

    // ---------------- final per-column mean centering -------------------
    zero_f<<<1, 256>>>(csum, 256);
    colsum_kernel<<<(NNODES + 63) / 64, 256>>>(out, csum);
    center_kernel<<<(NNODES * 256 + 255) / 256, 256>>>(out, csum);
}

// round 6
// speedup vs baseline: 4.4315x; 1.0087x over previous
#include <cuda_runtime.h>
#include <cuda_fp16.h>
#include <math.h>

#define NNODES 50000
#define NEDGES 800000
#define CH_SCAN 512
#define NB_SCAN ((NNODES + CH_SCAN - 1) / CH_SCAN)   // 98

// ---------------- scratch (static device globals; no allocations) ----------
__device__ __half g_z[2 * NNODES * 256];     // fp16 per-etype GEMM output
__device__ float g_h1[NNODES * 128];
__device__ float g_h2[NNODES * 64];
__device__ float g_el[2 * NNODES * 4];
__device__ float g_er[2 * NNODES * 4];
__device__ float g_colsum[256];
__device__ int   g_rp[2][NNODES + 1];        // CSR row pointers (by dst)
__device__ int   g_cse[2][NEDGES];           // CSR src indices
__device__ int   g_wp[2][NNODES];            // fill cursors
__device__ int   g_bsum[2][128];             // scan block sums (raw)

// ---------------- f32x2 packed-FMA helpers ----------------
__device__ __forceinline__ unsigned long long bcast2(float v) {
    unsigned long long r;
    asm("mov.b64 %0, {%1, %1};" : "=l"(r) : "f"(v));
    return r;
}
__device__ __forceinline__ void ffma2(unsigned long long& d,
                                      unsigned long long a, unsigned long long b) {
    asm("fma.rn.f32x2 %0, %1, %2, %0;" : "+l"(d) : "l"(a), "l"(b));
}
__device__ __forceinline__ float2 unpack2(unsigned long long v) {
    float2 f;
    asm("mov.b64 {%0, %1}, %2;" : "=f"(f.x), "=f"(f.y) : "l"(v));
    return f;
}

// ---------------- small utility kernels ----------------
__global__ void zero_int(int* p, int n) {
    int i = blockIdx.x * blockDim.x + threadIdx.x;
    if (i < n) p[i] = 0;
}
__global__ void zero_f(float* p, int n) {
    int i = blockIdx.x * blockDim.x + threadIdx.x;
    if (i < n) p[i] = 0.0f;
}

// ---------------- CSR build pieces ----------------
__global__ void scan_local(int* __restrict__ rpb, int* __restrict__ bsumb) {
    __shared__ int s[CH_SCAN];
    int* rp = rpb + blockIdx.y * (NNODES + 1);
    int* bsum = bsumb + blockIdx.y * 128;
    int tid = threadIdx.x;
    int i = blockIdx.x * CH_SCAN + tid;
    int v = (i < NNODES) ? rp[i] : 0;
    s[tid] = v;
    __syncthreads();
    for (int off = 1; off < CH_SCAN; off <<= 1) {
        int t = (tid >= off) ? s[tid - off] : 0;
        __syncthreads();
        s[tid] += t;
        __syncthreads();
    }
    if (i < NNODES) rp[i] = s[tid] - v;              // exclusive within block
    if (tid == CH_SCAN - 1) bsum[blockIdx.x] = s[tid];
}

__global__ void scan_add_wp(int* __restrict__ rpb, const int* __restrict__ bsumb,
                            int* __restrict__ wpb) {
    __shared__ int sb[128];
    int tid = threadIdx.x;
    if (tid < 128) {
        int v = (tid < NB_SCAN) ? bsumb[blockIdx.y * 128 + tid] : 0;
        sb[tid] = v;
    }
    __syncthreads();
    for (int off = 1; off < 128; off <<= 1) {
        int t = (tid < 128 && tid >= off) ? sb[tid - off] : 0;
        __syncthreads();
        if (tid < 128) sb[tid] += t;
        __syncthreads();
    }
    int i = blockIdx.x * blockDim.x + tid;
    int* rp = rpb + blockIdx.y * (NNODES + 1);
    int* wp = wpb + blockIdx.y * NNODES;
    if (i < NNODES) {
        int c = i / CH_SCAN;
        int pre = (c == 0) ? 0 : sb[c - 1];
        int v = rp[i] + pre;
        rp[i] = v;
        wp[i] = v;
    }
    if (i == 0) rp[NNODES] = NEDGES;
}

__global__ void fill_k(const int* __restrict__ s0, const int* __restrict__ s1,
                       const int* __restrict__ d0, const int* __restrict__ d1,
                       int* __restrict__ wpb, int* __restrict__ csb) {
    int e = blockIdx.x * blockDim.x + threadIdx.x;
    if (e >= NEDGES) return;
    const int* src = blockIdx.y ? s1 : s0;
    const int* dst = blockIdx.y ? d1 : d0;
    int* wp = wpb + blockIdx.y * NNODES;
    int* cs = csb + blockIdx.y * NEDGES;
    int p = atomicAdd(&wp[dst[e]], 1);
    cs[p] = src[e];
}

// ---------------- GEMM body (transposed X tile, f32x2 packed FMA) ----------
template <int K, int HF, int H>
__device__ __forceinline__ void
gemm_body(int bx, int by,
          const float* __restrict__ X, const float* __restrict__ Wb,
          const float* __restrict__ alb, const float* __restrict__ arb,
          __half* __restrict__ Zb, float* __restrict__ elb, float* __restrict__ erb) {
    constexpr int TN = 8, TM = 8, BK = 16;
    constexpr int TX = HF / TN;
    constexpr int TY = 256 / TX;
    constexpr int BM = TM * TY;
    constexpr int BMP = BM + 4;
    constexpr int RW = TX / H;

    __shared__ float xs[BK][BMP];              // transposed X tile
    __shared__ float ws[BK][HF];

    const float* W  = Wb  + by * K * HF;
    const float* al = alb + by * HF;
    const float* ar = arb + by * HF;
    __half* Z = Zb  + by * (NNODES * 256);
    float* el = elb + by * (NNODES * 4);
    float* er = erb + by * (NNODES * 4);

    int tid = threadIdx.x;
    int tx = tid % TX;
    int ty = tid / TX;
    int r0 = bx * BM;

    unsigned long long acc2[TM][TN / 2];       // packed fp32 pairs
#pragma unroll
    for (int i = 0; i < TM; i++)
#pragma unroll
        for (int j = 0; j < TN / 2; j++) acc2[i][j] = 0ull;

    for (int kb = 0; kb < K; kb += BK) {
#pragma unroll
        for (int idx = tid; idx < BM * BK / 4; idx += 256) {
            int lin = idx * 4;
            int r = lin / BK, c = lin % BK;
            int gr = r0 + r;
            float4 v = make_float4(0.f, 0.f, 0.f, 0.f);
            if (gr < NNODES) v = *(const float4*)&X[gr * K + kb + c];
            xs[c][r] = v.x; xs[c + 1][r] = v.y; xs[c + 2][r] = v.z; xs[c + 3][r] = v.w;
        }
#pragma unroll
        for (int idx = tid; idx < BK * HF / 4; idx += 256) {
            int lin = idx * 4;
            int r = lin / HF, c = lin % HF;
            *(float4*)&ws[r][c] = *(const float4*)&W[(kb + r) * HF + c];
        }
        __syncthreads();
#pragma unroll
        for (int kk = 0; kk < BK; kk++) {
            float4 a0 = *(const float4*)&xs[kk][ty * 8];
            float4 a1 = *(const float4*)&xs[kk][ty * 8 + 4];
            const unsigned long long* wp64 =
                (const unsigned long long*)&ws[kk][tx * 8];
            unsigned long long bp0 = wp64[0], bp1 = wp64[1],
                               bp2 = wp64[2], bp3 = wp64[3];
            unsigned long long ap[TM] = {
                bcast2(a0.x), bcast2(a0.y), bcast2(a0.z), bcast2(a0.w),
                bcast2(a1.x), bcast2(a1.y), bcast2(a1.z), bcast2(a1.w)};
#pragma unroll
            for (int i = 0; i < TM; i++) {
                ffma2(acc2[i][0], ap[i], bp0);
                ffma2(acc2[i][1], ap[i], bp1);
                ffma2(acc2[i][2], ap[i], bp2);
                ffma2(acc2[i][3], ap[i], bp3);
            }
        }
        __syncthreads();
    }

    int cbase = tx * TN;
#pragma unroll
    for (int i = 0; i < TM; i++) {
        int row = r0 + ty * TM + i;
        float2 u0 = unpack2(acc2[i][0]);
        float2 u1 = unpack2(acc2[i][1]);
        float2 u2 = unpack2(acc2[i][2]);
        float2 u3 = unpack2(acc2[i][3]);
        float av[TN] = {u0.x, u0.y, u1.x, u1.y, u2.x, u2.y, u3.x, u3.y};
        float pl = 0.0f, pr = 0.0f;
#pragma unroll
        for (int j = 0; j < TN; j++) {
            pl += av[j] * al[cbase + j];
            pr += av[j] * ar[cbase + j];
        }
#pragma unroll
        for (int o = RW / 2; o > 0; o >>= 1) {
            pl += __shfl_xor_sync(0xffffffffu, pl, o);
            pr += __shfl_xor_sync(0xffffffffu, pr, o);
        }
        if (row < NNODES) {
            uint4 pack;
            __half2* ph = (__half2*)&pack;
            ph[0] = __floats2half2_rn(av[0], av[1]);
            ph[1] = __floats2half2_rn(av[2], av[3]);
            ph[2] = __floats2half2_rn(av[4], av[5]);
            ph[3] = __floats2half2_rn(av[6], av[7]);
            *(uint4*)&Z[row * HF + cbase] = pack;
            if (tx % RW == 0) {
                int h = tx / RW;
                el[row * H + h] = pl;
                er[row * H + h] = pr;
            }
        }
    }
}

template <int K, int HF, int H>
__global__ void __launch_bounds__(256)
gemm_att(const float* __restrict__ X, const float* __restrict__ Wb,
         const float* __restrict__ alb, const float* __restrict__ arb,
         __half* __restrict__ Zb, float* __restrict__ elb, float* __restrict__ erb) {
    gemm_body<K, HF, H>(blockIdx.x, blockIdx.y, X, Wb, alb, arb, Zb, elb, erb);
}

// layer-1 GEMM fused with independent CSR edge counting (overlap on one wave)
__global__ void __launch_bounds__(256)
gemm1_count(const float* __restrict__ X, const float* __restrict__ Wb,
            const float* __restrict__ alb, const float* __restrict__ arb,
            __half* __restrict__ Zb, float* __restrict__ elb, float* __restrict__ erb,
            const int* __restrict__ d0, const int* __restrict__ d1,
            int* __restrict__ rpb, int gemmX, int countBlocks) {
    if ((int)blockIdx.x < gemmX) {
        gemm_body<128, 128, 1>(blockIdx.x, blockIdx.y, X, Wb, alb, arb, Zb, elb, erb);
    } else {
        int cb = blockIdx.x - gemmX;
        const int* dst = blockIdx.y ? d1 : d0;
        int* cnt = rpb + blockIdx.y * (NNODES + 1);
        for (int e = cb * 256 + threadIdx.x; e < NEDGES; e += countBlocks * 256)
            atomicAdd(&cnt[dst[e]], 1);
    }
}

// ---------------- single-pass CSR softmax + gather aggregation ----------------
__device__ __forceinline__ float lrelu(float v) {
    return (v > 0.0f) ? v : 0.2f * v;
}
__device__ __forceinline__ float2 h2f(const __half2 h) { return __half22float2(h); }

template <int HF, int H>
__global__ void __launch_bounds__(256)
gat_agg(const int* __restrict__ rp0, const int* __restrict__ cs0,
        const int* __restrict__ rp1, const int* __restrict__ cs1,
        const __half* __restrict__ z0, const __half* __restrict__ z1,
        const float* __restrict__ el0, const float* __restrict__ er0,
        const float* __restrict__ el1, const float* __restrict__ er1,
        const float* __restrict__ bia,     // (2, HF)
        const float* __restrict__ fc,      // nullptr -> c=0.5; else fc combine
        float* __restrict__ out,
        float* __restrict__ colsum) {      // non-null only for HF==256
    constexpr int VEC = HF / 32;
    __shared__ float scp[256];             // fused colsum partials (HF==256)
    if (HF == 256) {
        scp[threadIdx.x] = 0.0f;
        __syncthreads();
    }
    int w = (blockIdx.x * blockDim.x + threadIdx.x) >> 5;
    int lane = threadIdx.x & 31;

    float c0 = 0.5f, c1 = 0.5f;
    if (fc) { c0 = 0.5f * (fc[0] + fc[2]); c1 = 0.5f * (fc[1] + fc[3]); }

    float acc[VEC];
#pragma unroll
    for (int i = 0; i < VEC; i++) acc[i] = 0.0f;

    if (w < NNODES) {
#pragma unroll
        for (int et = 0; et < 2; et++) {
            const int* rp = et ? rp1 : rp0;
            const int* cs = et ? cs1 : cs0;
            const __half* z = et ? z1 : z0;
            const float* el = et ? el1 : el0;
            const float* er = et ? er1 : er0;
            float ce = et ? c1 : c0;

            int beg = rp[w];
            int end = rp[w + 1];
            if (beg == end) continue;

            float accE[VEC];
#pragma unroll
            for (int i = 0; i < VEC; i++) accE[i] = 0.0f;

            if constexpr (H == 1) {
                float ern = er[w];
                float den = 0.0f;
                int i = beg;
                for (; i + 4 <= end; i += 4) {
                    int sa = cs[i], sb = cs[i + 1], sc = cs[i + 2], sd = cs[i + 3];
                    float wa = __expf(lrelu(el[sa] + ern));
                    float wb = __expf(lrelu(el[sb] + ern));
                    float wc = __expf(lrelu(el[sc] + ern));
                    float wd = __expf(lrelu(el[sd] + ern));
                    if constexpr (HF == 128) {
                        uint2 pa = *(const uint2*)&z[sa * 128 + lane * 4];
                        uint2 pb = *(const uint2*)&z[sb * 128 + lane * 4];
                        uint2 pc = *(const uint2*)&z[sc * 128 + lane * 4];
                        uint2 pd = *(const uint2*)&z[sd * 128 + lane * 4];
                        float2 a0 = h2f(((const __half2*)&pa)[0]), a1 = h2f(((const __half2*)&pa)[1]);
                        float2 b0 = h2f(((const __half2*)&pb)[0]), b1 = h2f(((const __half2*)&pb)[1]);
                        float2 cc0 = h2f(((const __half2*)&pc)[0]), cc1 = h2f(((const __half2*)&pc)[1]);
                        float2 d0 = h2f(((const __half2*)&pd)[0]), d1 = h2f(((const __half2*)&pd)[1]);
                        accE[0] += wa * a0.x + wb * b0.x + wc * cc0.x + wd * d0.x;
                        accE[1] += wa * a0.y + wb * b0.y + wc * cc0.y + wd * d0.y;
                        accE[2] += wa * a1.x + wb * b1.x + wc * cc1.x + wd * d1.x;
                        accE[3] += wa * a1.y + wb * b1.y + wc * cc1.y + wd * d1.y;
                    } else {  // HF == 64
                        float2 a0 = h2f(*(const __half2*)&z[sa * 64 + lane * 2]);
                        float2 b0 = h2f(*(const __half2*)&z[sb * 64 + lane * 2]);
                        float2 cc0 = h2f(*(const __half2*)&z[sc * 64 + lane * 2]);
                        float2 d0 = h2f(*(const __half2*)&z[sd * 64 + lane * 2]);
                        accE[0] += wa * a0.x + wb * b0.x + wc * cc0.x + wd * d0.x;
                        accE[1] += wa * a0.y + wb * b0.y + wc * cc0.y + wd * d0.y;
                    }
                    den += wa + wb + wc + wd;
                }
                for (; i < end; i++) {
                    int s = cs[i];
                    float wt = __expf(lrelu(el[s] + ern));
                    den += wt;
                    if constexpr (HF == 128) {
                        uint2 p = *(const uint2*)&z[s * 128 + lane * 4];
                        float2 f0 = h2f(((const __half2*)&p)[0]);
                        float2 f1 = h2f(((const __half2*)&p)[1]);
                        accE[0] += wt * f0.x; accE[1] += wt * f0.y;
                        accE[2] += wt * f1.x; accE[3] += wt * f1.y;
                    } else {
                        float2 f0 = h2f(*(const __half2*)&z[s * 64 + lane * 2]);
                        accE[0] += wt * f0.x; accE[1] += wt * f0.y;
                    }
                }
                float sc1 = ce / fmaxf(den, 1e-30f);
#pragma unroll
                for (int j = 0; j < VEC; j++) acc[j] += accE[j] * sc1;
            } else {  // H == 4, HF == 256
                int h0 = lane >> 4;
                int h1 = 2 + (lane >> 4);
                float ern0 = er[w * 4 + h0];
                float ern1 = er[w * 4 + h1];
                float den0 = 0.0f, den1 = 0.0f;
                int i = beg;
                for (; i + 2 <= end; i += 2) {
                    int sa = cs[i], sb = cs[i + 1];
                    float wa0 = __expf(lrelu(el[sa * 4 + h0] + ern0));
                    float wa1 = __expf(lrelu(el[sa * 4 + h1] + ern1));
                    float wb0 = __expf(lrelu(el[sb * 4 + h0] + ern0));
                    float wb1 = __expf(lrelu(el[sb * 4 + h1] + ern1));
                    uint2 pa0 = *(const uint2*)&z[sa * 256 + lane * 4];
                    uint2 pa1 = *(const uint2*)&z[sa * 256 + 128 + lane * 4];
                    uint2 pb0 = *(const uint2*)&z[sb * 256 + lane * 4];
                    uint2 pb1 = *(const uint2*)&z[sb * 256 + 128 + lane * 4];
                    float2 a00 = h2f(((const __half2*)&pa0)[0]), a01 = h2f(((const __half2*)&pa0)[1]);
                    float2 a10 = h2f(((const __half2*)&pa1)[0]), a11 = h2f(((const __half2*)&pa1)[1]);
                    float2 b00 = h2f(((const __half2*)&pb0)[0]), b01 = h2f(((const __half2*)&pb0)[1]);
                    float2 b10 = h2f(((const __half2*)&pb1)[0]), b11 = h2f(((const __half2*)&pb1)[1]);
                    accE[0] += wa0 * a00.x + wb0 * b00.x;
                    accE[1] += wa0 * a00.y + wb0 * b00.y;
                    accE[2] += wa0 * a01.x + wb0 * b01.x;
                    accE[3] += wa0 * a01.y + wb0 * b01.y;
                    accE[4] += wa1 * a10.x + wb1 * b10.x;
                    accE[5] += wa1 * a10.y + wb1 * b10.y;
                    accE[6] += wa1 * a11.x + wb1 * b11.x;
                    accE[7] += wa1 * a11.y + wb1 * b11.y;
                    den0 += wa0 + wb0;
                    den1 += wa1 + wb1;
                }
                for (; i < end; i++) {
                    int s = cs[i];
                    float w0 = __expf(lrelu(el[s * 4 + h0] + ern0));
                    float w1 = __expf(lrelu(el[s * 4 + h1] + ern1));
                    uint2 p0 = *(const uint2*)&z[s * 256 + lane * 4];
                    uint2 p1 = *(const uint2*)&z[s * 256 + 128 + lane * 4];
                    float2 f00 = h2f(((const __half2*)&p0)[0]), f01 = h2f(((const __half2*)&p0)[1]);
                    float2 f10 = h2f(((const __half2*)&p1)[0]), f11 = h2f(((const __half2*)&p1)[1]);
                    accE[0] += w0 * f00.x; accE[1] += w0 * f00.y;
                    accE[2] += w0 * f01.x; accE[3] += w0 * f01.y;
                    accE[4] += w1 * f10.x; accE[5] += w1 * f10.y;
                    accE[6] += w1 * f11.x; accE[7] += w1 * f11.y;
                    den0 += w0;
                    den1 += w1;
                }
                float s0 = ce / fmaxf(den0, 1e-30f);
                float s1 = ce / fmaxf(den1, 1e-30f);
#pragma unroll
                for (int j = 0; j < 4; j++) acc[j] += accE[j] * s0;
#pragma unroll
                for (int j = 4; j < 8; j++) acc[j] += accE[j] * s1;
            }
        }

        // write output with combined bias
        if constexpr (HF == 64) {
            int f = lane * 2;
            float2 o;
            o.x = acc[0] + c0 * bia[f] + c1 * bia[64 + f];
            o.y = acc[1] + c0 * bia[f + 1] + c1 * bia[64 + f + 1];
            *(float2*)&out[w * 64 + f] = o;
        } else if constexpr (HF == 128) {
            int f = lane * 4;
            float4 o;
            o.x = acc[0] + c0 * bia[f + 0] + c1 * bia[128 + f + 0];
            o.y = acc[1] + c0 * bia[f + 1] + c1 * bia[128 + f + 1];
            o.z = acc[2] + c0 * bia[f + 2] + c1 * bia[128 + f + 2];
            o.w = acc[3] + c0 * bia[f + 3] + c1 * bia[128 + f + 3];
            *(float4*)&out[w * 128 + f] = o;
        } else {
            int f = lane * 4;
            float4 o0, o1;
            o0.x = acc[0] + c0 * bia[f + 0] + c1 * bia[256 + f + 0];
            o0.y = acc[1] + c0 * bia[f + 1] + c1 * bia[256 + f + 1];
            o0.z = acc[2] + c0 * bia[f + 2] + c1 * bia[256 + f + 2];
            o0.w = acc[3] + c0 * bia[f + 3] + c1 * bia[256 + f + 3];
            o1.x = acc[4] + c0 * bia[128 + f + 0] + c1 * bia[256 + 128 + f + 0];
            o1.y = acc[5] + c0 * bia[128 + f + 1] + c1 * bia[256 + 128 + f + 1];
            o1.z = acc[6] + c0 * bia[128 + f + 2] + c1 * bia[256 + 128 + f + 2];
            o1.w = acc[7] + c0 * bia[128 + f + 3] + c1 * bia[256 + 128 + f + 3];
            *(float4*)&out[w * 256 + f] = o0;
            *(float4*)&out[w * 256 + 128 + f] = o1;
            // fused column-sum partials
            atomicAdd(&scp[f + 0], o0.x);
            atomicAdd(&scp[f + 1], o0.y);
            atomicAdd(&scp[f + 2], o0.z);
            atomicAdd(&scp[f + 3], o0.w);
            atomicAdd(&scp[128 + f + 0], o1.x);
            atomicAdd(&scp[128 + f + 1], o1.y);
            atomicAdd(&scp[128 + f + 2], o1.z);
            atomicAdd(&scp[128 + f + 3], o1.w);
        }
    }

    if (HF == 256) {
        __syncthreads();
        atomicAdd(&colsum[threadIdx.x], scp[threadIdx.x]);
    }
}

// ---------------- final centering ----------------
__global__ void center_kernel(float* __restrict__ out, const float* __restrict__ cs) {
    int i = blockIdx.x * blockDim.x + threadIdx.x;
    if (i < NNODES * 256) out[i] -= cs[i & 255] * (1.0f / NNODES);
}

// ---------------- orchestration ----------------
extern "C" void kernel_launch(void* const* d_in, const int* in_sizes, int n_in,
                              void* d_out, int out_size) {
    const float* x   = (const float*)d_in[0];
    const int* src0 = (const int*)d_in[1];
    const int* dst0 = (const int*)d_in[2];
    const int* src1 = (const int*)d_in[3];
    const int* dst1 = (const int*)d_in[4];
    const float* W1  = (const float*)d_in[5];
    const float* al1 = (const float*)d_in[6];
    const float* ar1 = (const float*)d_in[7];
    const float* b1  = (const float*)d_in[8];
    const float* W2  = (const float*)d_in[9];
    const float* al2 = (const float*)d_in[10];
    const float* ar2 = (const float*)d_in[11];
    const float* b2  = (const float*)d_in[12];
    const float* Wm  = (const float*)d_in[13];
    const float* alm = (const float*)d_in[14];
    const float* arm = (const float*)d_in[15];
    const float* bm  = (const float*)d_in[16];
    const float* fc  = (const float*)d_in[17];
    float* out = (float*)d_out;

    __half* zb;
    float *h1, *h2, *elb, *erb, *csum;
    int *rpb, *cseb, *wpb, *bsumb;
    cudaGetSymbolAddress((void**)&zb,    g_z);
    cudaGetSymbolAddress((void**)&h1,    g_h1);
    cudaGetSymbolAddress((void**)&h2,    g_h2);
    cudaGetSymbolAddress((void**)&elb,   g_el);
    cudaGetSymbolAddress((void**)&erb,   g_er);
    cudaGetSymbolAddress((void**)&csum,  g_colsum);
    cudaGetSymbolAddress((void**)&rpb,   g_rp);
    cudaGetSymbolAddress((void**)&cseb,  g_cse);
    cudaGetSymbolAddress((void**)&wpb,   g_wp);
    cudaGetSymbolAddress((void**)&bsumb, g_bsum);

    int* rp[2]  = {rpb, rpb + (NNODES + 1)};
    int* cse[2] = {cseb, cseb + NEDGES};
    __half* z[2] = {zb, zb + NNODES * 256};
    float* el[2] = {elb, elb + NNODES * 4};
    float* er[2] = {erb, erb + NNODES * 4};

    const int EG = (NEDGES + 255) / 256;
    const int AGG_BLOCKS = (NNODES * 32 + 255) / 256;

    // ---------------- zero counters, then fused GEMM1 + edge count ---------
    zero_int<<<(2 * (NNODES + 1) + 255) / 256, 256>>>(rpb, 2 * (NNODES + 1));

    const int GEMM1_X = (NNODES + 127) / 128;        // BM=128 -> 391
    const int COUNT_B = 256;
    gemm1_count<<<dim3(GEMM1_X + COUNT_B, 2), 256>>>(
        x, W1, al1, ar1, zb, elb, erb, dst0, dst1, rpb, GEMM1_X, COUNT_B);

    // ---------------- finish CSR build ----------------
    scan_local<<<dim3(NB_SCAN, 2), CH_SCAN>>>(rpb, bsumb);
    scan_add_wp<<<dim3((NNODES + 255) / 256, 2), 256>>>(rpb, bsumb, wpb);
    fill_k<<<dim3(EG, 2), 256>>>(src0, src1, dst0, dst1, wpb, cseb);

    // ---------------- layer 1 aggregation ----------------
    gat_agg<128, 1><<<AGG_BLOCKS, 256>>>(
        rp[0], cse[0], rp[1], cse[1], z[0], z[1],
        el[0], er[0], el[1], er[1], b1, nullptr, h1, nullptr);

    // ---------------- layer 2: h1(128) -> h2(64), H=1, fc combine -------
    gemm_att<128, 64, 1><<<dim3((NNODES + 255) / 256, 2), 256>>>(
        h1, W2, al2, ar2, zb, elb, erb);
    gat_agg<64, 1><<<AGG_BLOCKS, 256>>>(
        rp[0], cse[0], rp[1], cse[1], z[0], z[1],
        el[0], er[0], el[1], er[1], b2, fc, h2, nullptr);

    // ---------------- layer MH: h2(64) -> out(4x64), H=4 ----------------
    gemm_att<64, 256, 4><<<dim3((NNODES + 63) / 64, 2), 256>>>(
        h2, Wm, alm, arm, zb, elb, erb);
    zero_f<<<1, 256>>>(csum, 256);
    gat_agg<256, 4><<<AGG_BLOCKS, 256>>>(
        rp[0], cse[0], rp[1], cse[1], z[0], z[1],
        el[0], er[0], el[1], er[1], bm, nullptr, out, csum);

    // ---------------- final per-column mean centering -------------------
    center_kernel<<<(NNODES * 256 + 255) / 256, 256>>>(out, csum);
}